// round 10
// baseline (speedup 1.0000x reference)
#include <cuda_runtime.h>
#include <cuda_fp16.h>
#include <math.h>
#include <stdint.h>

// Problem constants
#define BSZ    8
#define LSEQ   1024
#define DMODEL 1024
#define NSTATE 16
#define MTOT   (BSZ * LSEQ)        // 8192
#define XTOT   (MTOT * DMODEL)     // 8388608
#define KDIM   1024

// GEMM tiling (fp16 m16n8k16)
#define BM 128
#define BN 128
#define BK 32                       // halves per chunk (2 k16 steps)
#define NSTG 4
#define NCHUNK (KDIM / BK)          // 32
#define ROWB 80                     // bytes per 64B row + 16B pad (conflict-free)
#define ASTAGE_B (128 * ROWB)       // 10240
#define STAGE_B  (2 * ASTAGE_B)     // 20480
#define SMEM_DYN (NSTG * STAGE_B)   // 81920

// N sizes
#define N1 2048
#define N2 1152                     // 1024 dt + 16 B + 16 C + 96 pad
#define N3 1024

// ---------------------------------------------------------------------------
// Scratch
// ---------------------------------------------------------------------------
__device__ __align__(256) __half g_xnormh[XTOT];        // fp16 (gemm1 A)
__device__ __align__(256) float  g_xin[XTOT];           // fp32 (scan)
__device__ __align__(256) __half g_xinh[XTOT];          // fp16 (gemm2 A)
__device__ __align__(256) float  g_z[XTOT];
__device__ __align__(256) float  g_dt[XTOT];
__device__ __align__(256) float  g_Bt[MTOT * NSTATE];
__device__ __align__(256) float  g_Ct[MTOT * NSTATE];
__device__ __align__(256) __half g_ssmh[XTOT];          // fp16 (gemm3 A)
__device__ __align__(256) __half g_wigh[N1 * KDIM];     // fp16 W_ig
__device__ __align__(256) __half g_wbch[N2 * KDIM];     // fp16 [W_dt;W_B;W_C;0]
__device__ __align__(256) __half g_wouth[N3 * KDIM];    // fp16 W_out

// ---------------------------------------------------------------------------
// Helpers
// ---------------------------------------------------------------------------
__device__ __forceinline__ uint32_t pack_h2(float a, float b) {
    __half2 h = __floats2half2_rn(a, b);
    return *reinterpret_cast<uint32_t*>(&h);
}

__device__ __forceinline__ void mma_f16(float* c, const uint32_t* a, const uint32_t* b) {
    asm volatile(
        "mma.sync.aligned.m16n8k16.row.col.f32.f16.f16.f32 "
        "{%0,%1,%2,%3}, {%4,%5,%6,%7}, {%8,%9}, {%0,%1,%2,%3};"
        : "+f"(c[0]), "+f"(c[1]), "+f"(c[2]), "+f"(c[3])
        : "r"(a[0]), "r"(a[1]), "r"(a[2]), "r"(a[3]), "r"(b[0]), "r"(b[1]));
}

__device__ __forceinline__ uint32_t smem_u32(const void* p) {
    uint32_t a;
    asm("{ .reg .u64 t; cvta.to.shared.u64 t, %1; cvt.u32.u64 %0, t; }" : "=r"(a) : "l"(p));
    return a;
}
__device__ __forceinline__ void cp16(uint32_t dst, const void* src) {
    asm volatile("cp.async.cg.shared.global [%0], [%1], 16;"
                 :: "r"(dst), "l"(__cvta_generic_to_global(src)));
}
#define CP_COMMIT() asm volatile("cp.async.commit_group;")
#define CP_WAIT2()  asm volatile("cp.async.wait_group 2;" ::: "memory")

__device__ __forceinline__ float softplus_f(float v) {
    return (v > 20.f) ? v : log1pf(expf(v));
}

// ---------------------------------------------------------------------------
// LayerNorm -> fp16 x_norm (only consumer is gemm1's A)
// ---------------------------------------------------------------------------
__global__ __launch_bounds__(256) void layernorm_kernel(
    const float* __restrict__ x,
    const float* __restrict__ g,
    const float* __restrict__ b)
{
    int row = blockIdx.x;
    int t = threadIdx.x;
    float4 v = reinterpret_cast<const float4*>(x + (size_t)row * DMODEL)[t];

    float s  = v.x + v.y + v.z + v.w;
    float sq = v.x * v.x + v.y * v.y + v.z * v.z + v.w * v.w;
    #pragma unroll
    for (int o = 16; o; o >>= 1) {
        s  += __shfl_xor_sync(0xffffffffu, s,  o);
        sq += __shfl_xor_sync(0xffffffffu, sq, o);
    }
    __shared__ float ssum[8], ssq[8], sh_mean, sh_rstd;
    int w = t >> 5;
    if ((t & 31) == 0) { ssum[w] = s; ssq[w] = sq; }
    __syncthreads();
    if (t == 0) {
        float S = 0.f, Q = 0.f;
        #pragma unroll
        for (int i = 0; i < 8; i++) { S += ssum[i]; Q += ssq[i]; }
        float mu  = S * (1.0f / DMODEL);
        float var = Q * (1.0f / DMODEL) - mu * mu;
        sh_mean = mu;
        sh_rstd = rsqrtf(var + 1e-5f);
    }
    __syncthreads();
    float mean = sh_mean, rstd = sh_rstd;

    float4 gg = reinterpret_cast<const float4*>(g)[t];
    float4 bb = reinterpret_cast<const float4*>(b)[t];
    uint2 o;
    o.x = pack_h2((v.x - mean) * rstd * gg.x + bb.x,
                  (v.y - mean) * rstd * gg.y + bb.y);
    o.y = pack_h2((v.z - mean) * rstd * gg.z + bb.z,
                  (v.w - mean) * rstd * gg.w + bb.w);
    reinterpret_cast<uint2*>(g_xnormh + (size_t)row * DMODEL)[t] = o;
}

// ---------------------------------------------------------------------------
// Weight prep: fp16-convert all B operands; assemble fused [W_dt; W_B; W_C; 0]
// (rows 1056..1151 of g_wbch stay zero from static init)
// ---------------------------------------------------------------------------
__global__ __launch_bounds__(256) void prep_kernel(
    const float* __restrict__ W_ig,
    const float* __restrict__ W_dt,
    const float* __restrict__ W_B,
    const float* __restrict__ W_C,
    const float* __restrict__ W_out)
{
    const int K4 = KDIM / 4;
    int stride = gridDim.x * blockDim.x;
    const int nig  = N1 * K4;
    const int nbc  = 1056 * K4;
    const int nout = N3 * K4;
    int total = nig + nbc + nout;
    for (int i = blockIdx.x * blockDim.x + threadIdx.x; i < total; i += stride) {
        const float4* src;
        __half* dst;
        if (i < nig) {
            src = reinterpret_cast<const float4*>(W_ig) + i;
            dst = g_wigh + (size_t)i * 4;
        } else if (i < nig + nbc) {
            int j = i - nig;
            int row = j / K4;
            int c4  = j % K4;
            const float* s;
            if (row < 1024)      s = W_dt + (size_t)row * KDIM;
            else if (row < 1040) s = W_B + (size_t)(row - 1024) * KDIM;
            else                 s = W_C + (size_t)(row - 1040) * KDIM;
            src = reinterpret_cast<const float4*>(s) + c4;
            dst = g_wbch + (size_t)j * 4;
        } else {
            int j = i - nig - nbc;
            src = reinterpret_cast<const float4*>(W_out) + j;
            dst = g_wouth + (size_t)j * 4;
        }
        float4 v = *src;
        uint2 o;
        o.x = pack_h2(v.x, v.y);
        o.y = pack_h2(v.z, v.w);
        *reinterpret_cast<uint2*>(dst) = o;
    }
}

// ---------------------------------------------------------------------------
// FP16 mma.sync m16n8k16 GEMM, cp.async 4-stage pipeline (2-chunk prefetch).
// C[m,n] = sum_k A[m,k]*B[n,k]; tile 128x128, 8 warps (2m x 4n), warp 64x32.
// SMEM: k-major rows of 64B (+16B pad -> 20-word stride, conflict-free).
// EPI 1: n<1024 -> O0 (fp32 x_in) + O2h (fp16 copy); else O1 (z, fp32)
// EPI 2: n<1024 -> softplus(v+aux[n]) -> O0; 1024-1039 -> O1(Bt);
//        1040-1055 -> O2(Ct); else discard
// EPI 3: O0 = v + aux[m*1024+n]
// ---------------------------------------------------------------------------
template<int EPI>
__global__ __launch_bounds__(256, 2) void gemm_ma(
    const __half* __restrict__ A,
    const __half* __restrict__ Bw,
    float* __restrict__ O0,
    float* __restrict__ O1,
    float* __restrict__ O2,
    __half* __restrict__ O2h,
    const float* __restrict__ aux)
{
    extern __shared__ char dsm[];
    const uint32_t dsm_addr = smem_u32(dsm);

    const int tid  = threadIdx.x;
    const int wid  = tid >> 5;
    const int lane = tid & 31;
    const int bm   = blockIdx.y * BM;
    const int bn   = blockIdx.x * BN;
    const int wm   = wid >> 2;
    const int wn   = wid & 3;
    const int g    = lane >> 2;
    const int t4   = lane & 3;

    const __half* Ag = A  + (size_t)bm * KDIM;
    const __half* Bg = Bw + (size_t)bn * KDIM;

    const int lrow = tid >> 2;      // 0..63 (+it*64)
    const int lc16 = tid & 3;       // 16B column 0..3

    auto load_chunk = [&](int c, int stg) {
        uint32_t base = dsm_addr + (uint32_t)(stg * STAGE_B);
        #pragma unroll
        for (int it = 0; it < 2; it++) {
            int row = lrow + it * 64;
            cp16(base + (uint32_t)(row * ROWB + lc16 * 16),
                 Ag + (size_t)row * KDIM + c * BK + lc16 * 8);
        }
        uint32_t baseB = base + ASTAGE_B;
        #pragma unroll
        for (int it = 0; it < 2; it++) {
            int row = lrow + it * 64;
            cp16(baseB + (uint32_t)(row * ROWB + lc16 * 16),
                 Bg + (size_t)row * KDIM + c * BK + lc16 * 8);
        }
    };

    float acc[4][4][4];
    #pragma unroll
    for (int i = 0; i < 4; i++)
        #pragma unroll
        for (int j = 0; j < 4; j++)
            #pragma unroll
            for (int r = 0; r < 4; r++) acc[i][j][r] = 0.f;

    // prologue: chunks 0,1,2
    load_chunk(0, 0); CP_COMMIT();
    load_chunk(1, 1); CP_COMMIT();
    load_chunk(2, 2); CP_COMMIT();

    for (int c = 0; c < NCHUNK; c++) {
        CP_WAIT2();           // chunk c's loads complete (2 younger in flight)
        __syncthreads();      // every warp done computing chunk c-1 ->
                              // stage (c+3)%4 == (c-1)%4 reusable

        if (c + 3 < NCHUNK) { load_chunk(c + 3, (c + 3) & (NSTG - 1)); CP_COMMIT(); }

        const char* sA = dsm + (c & (NSTG - 1)) * STAGE_B;
        const char* sAm = sA + (wm * 64) * ROWB + 4 * t4;
        const char* sBn = sA + ASTAGE_B + (wn * 32) * ROWB + 4 * t4;

        #pragma unroll
        for (int s = 0; s < 2; s++) {
            const int ko = s * 32;   // byte offset of this k16 step
            uint32_t bf[4][2];
            #pragma unroll
            for (int nt = 0; nt < 4; nt++) {
                const char* p = sBn + (nt * 8 + g) * ROWB + ko;
                bf[nt][0] = *reinterpret_cast<const uint32_t*>(p);
                bf[nt][1] = *reinterpret_cast<const uint32_t*>(p + 16);
            }
            #pragma unroll
            for (int mt = 0; mt < 4; mt++) {
                uint32_t af[4];
                const char* p0 = sAm + (mt * 16 + g) * ROWB + ko;
                const char* p1 = p0 + 8 * ROWB;
                af[0] = *reinterpret_cast<const uint32_t*>(p0);
                af[1] = *reinterpret_cast<const uint32_t*>(p1);
                af[2] = *reinterpret_cast<const uint32_t*>(p0 + 16);
                af[3] = *reinterpret_cast<const uint32_t*>(p1 + 16);
                #pragma unroll
                for (int nt = 0; nt < 4; nt++)
                    mma_f16(acc[mt][nt], af, bf[nt]);
            }
        }
    }

    // Epilogue
    #pragma unroll
    for (int mt = 0; mt < 4; mt++) {
        #pragma unroll
        for (int nt = 0; nt < 4; nt++) {
            int m0 = bm + wm * 64 + mt * 16 + g;
            int n0 = bn + wn * 32 + nt * 8 + 2 * t4;
            float* cc = acc[mt][nt];
            #pragma unroll
            for (int half_i = 0; half_i < 2; half_i++) {
                int m = m0 + half_i * 8;
                float v0 = cc[half_i * 2 + 0];
                float v1 = cc[half_i * 2 + 1];
                if constexpr (EPI == 1) {
                    if (n0 < DMODEL) {
                        *reinterpret_cast<float2*>(&O0[(size_t)m * DMODEL + n0]) = make_float2(v0, v1);
                        *reinterpret_cast<uint32_t*>(&O2h[(size_t)m * DMODEL + n0]) = pack_h2(v0, v1);
                    } else {
                        *reinterpret_cast<float2*>(&O1[(size_t)m * DMODEL + n0 - DMODEL]) = make_float2(v0, v1);
                    }
                } else if constexpr (EPI == 2) {
                    if (n0 < DMODEL) {
                        v0 = softplus_f(v0 + aux[n0]);
                        v1 = softplus_f(v1 + aux[n0 + 1]);
                        *reinterpret_cast<float2*>(&O0[(size_t)m * DMODEL + n0]) = make_float2(v0, v1);
                    } else if (n0 < 1040) {
                        *reinterpret_cast<float2*>(&O1[(size_t)m * NSTATE + (n0 - 1024)]) = make_float2(v0, v1);
                    } else if (n0 < 1056) {
                        *reinterpret_cast<float2*>(&O2[(size_t)m * NSTATE + (n0 - 1040)]) = make_float2(v0, v1);
                    }
                } else { // EPI == 3
                    float2 r = *reinterpret_cast<const float2*>(&aux[(size_t)m * DMODEL + n0]);
                    *reinterpret_cast<float2*>(&O0[(size_t)m * DMODEL + n0]) = make_float2(v0 + r.x, v1 + r.y);
                }
            }
        }
    }
}

// ---------------------------------------------------------------------------
// Sequential SSM scan + fused silu/D epilogue, 1-step-ahead prefetch.
// ssm written fp16 (only consumer is gemm3's A operand).
// ---------------------------------------------------------------------------
__global__ __launch_bounds__(256) void scan_kernel(
    const float* __restrict__ A_log,
    const float* __restrict__ h_prev,
    const float* __restrict__ Dvec,
    float* __restrict__ h_out)
{
    int b  = blockIdx.x >> 6;
    int dg = blockIdx.x & 63;
    int n  = threadIdx.x & 15;
    int dl = threadIdx.x >> 4;
    int d  = dg * 16 + dl;

    float Acoef = -__expf(A_log[d * NSTATE + n]);
    float h  = h_prev[((size_t)b * DMODEL + d) * NSTATE + n];
    float Dd = Dvec[d];
    const bool lead = (n == 0);

    size_t idx  = (size_t)b * LSEQ * DMODEL + d;
    size_t idxn = (size_t)b * LSEQ * NSTATE + n;

    float dtv = g_dt[idx];
    float xin = g_xin[idx];
    float Btv = g_Bt[idxn];
    float Ctv = g_Ct[idxn];
    float zv  = lead ? g_z[idx] : 0.f;

    for (int t = 0; t < LSEQ; t++) {
        float n_dt = 0.f, n_xin = 0.f, n_Bt = 0.f, n_Ct = 0.f, n_z = 0.f;
        if (t + 1 < LSEQ) {
            n_dt  = g_dt[idx + DMODEL];
            n_xin = g_xin[idx + DMODEL];
            n_Bt  = g_Bt[idxn + NSTATE];
            n_Ct  = g_Ct[idxn + NSTATE];
            if (lead) n_z = g_z[idx + DMODEL];
        }

        float dA = __expf(dtv * Acoef);
        h = dA * h + (dtv * xin) * Btv;
        float y = h * Ctv;
        y += __shfl_xor_sync(0xffffffffu, y, 1);
        y += __shfl_xor_sync(0xffffffffu, y, 2);
        y += __shfl_xor_sync(0xffffffffu, y, 4);
        y += __shfl_xor_sync(0xffffffffu, y, 8);

        if (lead) {
            float sil = zv / (1.f + __expf(-zv));
            g_ssmh[idx] = __float2half_rn(y * sil + xin * Dd);
        }

        dtv = n_dt; xin = n_xin; Btv = n_Bt; Ctv = n_Ct; zv = n_z;
        idx += DMODEL; idxn += NSTATE;
    }
    h_out[((size_t)b * DMODEL + d) * NSTATE + n] = h;
}

// ---------------------------------------------------------------------------
// Launch
// ---------------------------------------------------------------------------
extern "C" void kernel_launch(void* const* d_in, const int* in_sizes, int n_in,
                              void* d_out, int out_size)
{
    const float* x      = (const float*)d_in[0];
    const float* h_prev = (const float*)d_in[1];
    const float* ln_g   = (const float*)d_in[2];
    const float* ln_b   = (const float*)d_in[3];
    const float* W_ig   = (const float*)d_in[4];
    const float* W_dt   = (const float*)d_in[5];
    const float* b_dt   = (const float*)d_in[6];
    const float* A_log  = (const float*)d_in[7];
    const float* W_B    = (const float*)d_in[8];
    const float* W_C    = (const float*)d_in[9];
    const float* Dv     = (const float*)d_in[10];
    const float* W_out  = (const float*)d_in[11];
    float* out = (float*)d_out;

    float *p_xin, *p_z, *p_dt, *p_Bt, *p_Ct;
    __half *p_xnormh, *p_xinh, *p_ssmh, *p_wigh, *p_wbch, *p_wouth;
    cudaGetSymbolAddress((void**)&p_xnormh, g_xnormh);
    cudaGetSymbolAddress((void**)&p_xin,    g_xin);
    cudaGetSymbolAddress((void**)&p_xinh,   g_xinh);
    cudaGetSymbolAddress((void**)&p_z,      g_z);
    cudaGetSymbolAddress((void**)&p_dt,     g_dt);
    cudaGetSymbolAddress((void**)&p_Bt,     g_Bt);
    cudaGetSymbolAddress((void**)&p_Ct,     g_Ct);
    cudaGetSymbolAddress((void**)&p_ssmh,   g_ssmh);
    cudaGetSymbolAddress((void**)&p_wigh,   g_wigh);
    cudaGetSymbolAddress((void**)&p_wbch,   g_wbch);
    cudaGetSymbolAddress((void**)&p_wouth,  g_wouth);

    cudaFuncSetAttribute(gemm_ma<1>, cudaFuncAttributeMaxDynamicSharedMemorySize, SMEM_DYN);
    cudaFuncSetAttribute(gemm_ma<2>, cudaFuncAttributeMaxDynamicSharedMemorySize, SMEM_DYN);
    cudaFuncSetAttribute(gemm_ma<3>, cudaFuncAttributeMaxDynamicSharedMemorySize, SMEM_DYN);

    // 0. weight prep (fp16 conversion + fused W' assembly)
    prep_kernel<<<2048, 256>>>(W_ig, W_dt, W_B, W_C, W_out);

    // 1. LayerNorm (fp16 output)
    layernorm_kernel<<<MTOT, 256>>>(x, ln_g, ln_b);

    // 2. x_proj = x_norm @ W_ig^T -> x_in (fp32 + fp16 copy) | z
    {
        dim3 grid(N1 / BN, MTOT / BM);
        gemm_ma<1><<<grid, 256, SMEM_DYN>>>(p_xnormh, p_wigh, p_xin, p_z, nullptr, p_xinh, nullptr);
    }

    // 3. fused: dt = softplus(x_in@W_dt^T + b_dt); Bt; Ct
    {
        dim3 grid(N2 / BN, MTOT / BM);
        gemm_ma<2><<<grid, 256, SMEM_DYN>>>(p_xinh, p_wbch, p_dt, p_Bt, p_Ct, nullptr, b_dt);
    }

    // 4. scan -> g_ssmh (fp16), h_final -> out tail
    scan_kernel<<<BSZ * 64, 256>>>(A_log, h_prev, Dv, out + XTOT);

    // 5. out = x + ssm @ W_out^T
    {
        dim3 grid(N3 / BN, MTOT / BM);
        gemm_ma<3><<<grid, 256, SMEM_DYN>>>(p_ssmh, p_wouth, out, nullptr, nullptr, nullptr, x);
    }
}

// round 11
// speedup vs baseline: 1.1793x; 1.1793x over previous
#include <cuda_runtime.h>
#include <cuda_fp16.h>
#include <math.h>
#include <stdint.h>

// Problem constants
#define BSZ    8
#define LSEQ   1024
#define DMODEL 1024
#define NSTATE 16
#define MTOT   (BSZ * LSEQ)        // 8192
#define XTOT   (MTOT * DMODEL)     // 8388608
#define KDIM   1024

// GEMM tiling (fp16 m16n8k16)
#define BM 128
#define BN 128
#define BK 32                       // halves per chunk (2 k16 steps)
#define NSTG 4
#define NCHUNK (KDIM / BK)          // 32
#define ROWB 80                     // 64B row + 16B pad (conflict-free, also for ldmatrix)
#define ASTAGE_B (128 * ROWB)       // 10240
#define STAGE_B  (2 * ASTAGE_B)     // 20480
#define SMEM_DYN (NSTG * STAGE_B)   // 81920

// N sizes
#define N1 2048
#define N2 1152                     // 1024 dt + 16 B + 16 C + 96 pad
#define N3 1024

// ---------------------------------------------------------------------------
// Scratch
// ---------------------------------------------------------------------------
__device__ __align__(256) __half g_xnormh[XTOT];        // fp16 (gemm1 A)
__device__ __align__(256) __half g_xinh[XTOT];          // fp16 row-major (gemm2 A)
__device__ __align__(256) __half g_xinT[XTOT];          // fp16 [b][d][t] (scan)
__device__ __align__(256) __half g_zT[XTOT];            // fp16 [b][d][t] (scan)
__device__ __align__(256) __half g_dtT[XTOT];           // fp16 [b][d][t] (scan)
__device__ __align__(256) __half g_btT[MTOT * NSTATE];  // fp16 [b][n][t]
__device__ __align__(256) __half g_ctT[MTOT * NSTATE];  // fp16 [b][n][t]
__device__ __align__(256) __half g_ssmh[XTOT];          // fp16 row-major (gemm3 A)
__device__ __align__(256) __half g_wigh[N1 * KDIM];     // fp16 W_ig
__device__ __align__(256) __half g_wbch[N2 * KDIM];     // fp16 [W_dt;W_B;W_C;0]
__device__ __align__(256) __half g_wouth[N3 * KDIM];    // fp16 W_out

// ---------------------------------------------------------------------------
// Helpers
// ---------------------------------------------------------------------------
__device__ __forceinline__ uint32_t pack_h2(float a, float b) {
    __half2 h = __floats2half2_rn(a, b);
    return *reinterpret_cast<uint32_t*>(&h);
}

__device__ __forceinline__ void mma_f16(float* c, const uint32_t* a, const uint32_t* b) {
    asm volatile(
        "mma.sync.aligned.m16n8k16.row.col.f32.f16.f16.f32 "
        "{%0,%1,%2,%3}, {%4,%5,%6,%7}, {%8,%9}, {%0,%1,%2,%3};"
        : "+f"(c[0]), "+f"(c[1]), "+f"(c[2]), "+f"(c[3])
        : "r"(a[0]), "r"(a[1]), "r"(a[2]), "r"(a[3]), "r"(b[0]), "r"(b[1]));
}

__device__ __forceinline__ void ldmx4(uint32_t& r0, uint32_t& r1, uint32_t& r2,
                                      uint32_t& r3, uint32_t addr) {
    asm volatile("ldmatrix.sync.aligned.m8n8.x4.shared.b16 {%0,%1,%2,%3}, [%4];"
                 : "=r"(r0), "=r"(r1), "=r"(r2), "=r"(r3) : "r"(addr));
}

__device__ __forceinline__ uint32_t smem_u32(const void* p) {
    uint32_t a;
    asm("{ .reg .u64 t; cvta.to.shared.u64 t, %1; cvt.u32.u64 %0, t; }" : "=r"(a) : "l"(p));
    return a;
}
__device__ __forceinline__ void cp16(uint32_t dst, const void* src) {
    asm volatile("cp.async.cg.shared.global [%0], [%1], 16;"
                 :: "r"(dst), "l"(__cvta_generic_to_global(src)));
}
#define CP_COMMIT() asm volatile("cp.async.commit_group;")
#define CP_WAIT2()  asm volatile("cp.async.wait_group 2;" ::: "memory")

__device__ __forceinline__ float softplus_f(float v) {
    return (v > 20.f) ? v : log1pf(expf(v));
}

// ---------------------------------------------------------------------------
// LayerNorm -> fp16 x_norm (only consumer is gemm1's A)
// ---------------------------------------------------------------------------
__global__ __launch_bounds__(256) void layernorm_kernel(
    const float* __restrict__ x,
    const float* __restrict__ g,
    const float* __restrict__ b)
{
    int row = blockIdx.x;
    int t = threadIdx.x;
    float4 v = reinterpret_cast<const float4*>(x + (size_t)row * DMODEL)[t];

    float s  = v.x + v.y + v.z + v.w;
    float sq = v.x * v.x + v.y * v.y + v.z * v.z + v.w * v.w;
    #pragma unroll
    for (int o = 16; o; o >>= 1) {
        s  += __shfl_xor_sync(0xffffffffu, s,  o);
        sq += __shfl_xor_sync(0xffffffffu, sq, o);
    }
    __shared__ float ssum[8], ssq[8], sh_mean, sh_rstd;
    int w = t >> 5;
    if ((t & 31) == 0) { ssum[w] = s; ssq[w] = sq; }
    __syncthreads();
    if (t == 0) {
        float S = 0.f, Q = 0.f;
        #pragma unroll
        for (int i = 0; i < 8; i++) { S += ssum[i]; Q += ssq[i]; }
        float mu  = S * (1.0f / DMODEL);
        float var = Q * (1.0f / DMODEL) - mu * mu;
        sh_mean = mu;
        sh_rstd = rsqrtf(var + 1e-5f);
    }
    __syncthreads();
    float mean = sh_mean, rstd = sh_rstd;

    float4 gg = reinterpret_cast<const float4*>(g)[t];
    float4 bb = reinterpret_cast<const float4*>(b)[t];
    uint2 o;
    o.x = pack_h2((v.x - mean) * rstd * gg.x + bb.x,
                  (v.y - mean) * rstd * gg.y + bb.y);
    o.y = pack_h2((v.z - mean) * rstd * gg.z + bb.z,
                  (v.w - mean) * rstd * gg.w + bb.w);
    reinterpret_cast<uint2*>(g_xnormh + (size_t)row * DMODEL)[t] = o;
}

// ---------------------------------------------------------------------------
// Weight prep: fp16-convert all B operands; assemble fused [W_dt; W_B; W_C; 0]
// ---------------------------------------------------------------------------
__global__ __launch_bounds__(256) void prep_kernel(
    const float* __restrict__ W_ig,
    const float* __restrict__ W_dt,
    const float* __restrict__ W_B,
    const float* __restrict__ W_C,
    const float* __restrict__ W_out)
{
    const int K4 = KDIM / 4;
    int stride = gridDim.x * blockDim.x;
    const int nig  = N1 * K4;
    const int nbc  = 1056 * K4;
    const int nout = N3 * K4;
    int total = nig + nbc + nout;
    for (int i = blockIdx.x * blockDim.x + threadIdx.x; i < total; i += stride) {
        const float4* src;
        __half* dst;
        if (i < nig) {
            src = reinterpret_cast<const float4*>(W_ig) + i;
            dst = g_wigh + (size_t)i * 4;
        } else if (i < nig + nbc) {
            int j = i - nig;
            int row = j / K4;
            int c4  = j % K4;
            const float* s;
            if (row < 1024)      s = W_dt + (size_t)row * KDIM;
            else if (row < 1040) s = W_B + (size_t)(row - 1024) * KDIM;
            else                 s = W_C + (size_t)(row - 1040) * KDIM;
            src = reinterpret_cast<const float4*>(s) + c4;
            dst = g_wbch + (size_t)j * 4;
        } else {
            int j = i - nig - nbc;
            src = reinterpret_cast<const float4*>(W_out) + j;
            dst = g_wouth + (size_t)j * 4;
        }
        float4 v = *src;
        uint2 o;
        o.x = pack_h2(v.x, v.y);
        o.y = pack_h2(v.z, v.w);
        *reinterpret_cast<uint2*>(dst) = o;
    }
}

// ---------------------------------------------------------------------------
// FP16 mma.sync m16n8k16 GEMM, cp.async 4-stage pipeline, ldmatrix fragments.
// Tile 128x128, 8 warps (2m x 4n), warp 64x32.
// EPI 1: n<1024 -> g_xinh (row-major) + g_xinT (time-major); else g_zT
// EPI 2: n<1024 -> softplus(v+aux[n]) -> g_dtT; 1024-1039 -> g_btT;
//        1040-1055 -> g_ctT; else discard
// EPI 3: O0 = v + aux[m*1024+n]  (fp32 row-major)
// ---------------------------------------------------------------------------
template<int EPI>
__global__ __launch_bounds__(256, 2) void gemm_ma(
    const __half* __restrict__ A,
    const __half* __restrict__ Bw,
    float* __restrict__ O0,
    const float* __restrict__ aux)
{
    extern __shared__ char dsm[];
    const uint32_t dsm_addr = smem_u32(dsm);

    const int tid  = threadIdx.x;
    const int wid  = tid >> 5;
    const int lane = tid & 31;
    const int bm   = blockIdx.y * BM;
    const int bn   = blockIdx.x * BN;
    const int wm   = wid >> 2;
    const int wn   = wid & 3;
    const int g    = lane >> 2;
    const int t4   = lane & 3;

    const __half* Ag = A  + (size_t)bm * KDIM;
    const __half* Bg = Bw + (size_t)bn * KDIM;

    const int lrow = tid >> 2;      // 0..63 (+it*64)
    const int lc16 = tid & 3;       // 16B column 0..3

    auto load_chunk = [&](int c, int stg) {
        uint32_t base = dsm_addr + (uint32_t)(stg * STAGE_B);
        #pragma unroll
        for (int it = 0; it < 2; it++) {
            int row = lrow + it * 64;
            cp16(base + (uint32_t)(row * ROWB + lc16 * 16),
                 Ag + (size_t)row * KDIM + c * BK + lc16 * 8);
        }
        uint32_t baseB = base + ASTAGE_B;
        #pragma unroll
        for (int it = 0; it < 2; it++) {
            int row = lrow + it * 64;
            cp16(baseB + (uint32_t)(row * ROWB + lc16 * 16),
                 Bg + (size_t)row * KDIM + c * BK + lc16 * 8);
        }
    };

    // ldmatrix per-lane row/offset patterns
    const int rowA  = (lane & 7) + ((lane >> 3) & 1) * 8;  // A: m within 16
    const int koffA = (lane >> 4) * 16;                    // A: k-half select
    const int rowB  = (lane & 7) + (lane >> 4) * 8;        // B: n within 16
    const int koffB = ((lane >> 3) & 1) * 16;              // B: k-half select

    float acc[4][4][4];
    #pragma unroll
    for (int i = 0; i < 4; i++)
        #pragma unroll
        for (int j = 0; j < 4; j++)
            #pragma unroll
            for (int r = 0; r < 4; r++) acc[i][j][r] = 0.f;

    // prologue: chunks 0,1,2
    load_chunk(0, 0); CP_COMMIT();
    load_chunk(1, 1); CP_COMMIT();
    load_chunk(2, 2); CP_COMMIT();

    for (int c = 0; c < NCHUNK; c++) {
        CP_WAIT2();
        __syncthreads();

        if (c + 3 < NCHUNK) { load_chunk(c + 3, (c + 3) & (NSTG - 1)); CP_COMMIT(); }

        uint32_t sbase = dsm_addr + (uint32_t)((c & (NSTG - 1)) * STAGE_B);
        uint32_t aAddr = sbase + (uint32_t)((wm * 64 + rowA) * ROWB + koffA);
        uint32_t bAddr = sbase + ASTAGE_B + (uint32_t)((wn * 32 + rowB) * ROWB + koffB);

        #pragma unroll
        for (int s = 0; s < 2; s++) {
            const int ko = s * 32;   // byte offset of this k16 step
            uint32_t bf[4][2];
            #pragma unroll
            for (int np = 0; np < 2; np++)
                ldmx4(bf[2 * np][0], bf[2 * np][1], bf[2 * np + 1][0], bf[2 * np + 1][1],
                      bAddr + (uint32_t)(np * 16 * ROWB + ko));
            #pragma unroll
            for (int mt = 0; mt < 4; mt++) {
                uint32_t af[4];
                ldmx4(af[0], af[1], af[2], af[3],
                      aAddr + (uint32_t)(mt * 16 * ROWB + ko));
                #pragma unroll
                for (int nt = 0; nt < 4; nt++)
                    mma_f16(acc[mt][nt], af, bf[nt]);
            }
        }
    }

    // Epilogue
    #pragma unroll
    for (int mt = 0; mt < 4; mt++) {
        #pragma unroll
        for (int nt = 0; nt < 4; nt++) {
            int m0 = bm + wm * 64 + mt * 16 + g;
            int n0 = bn + wn * 32 + nt * 8 + 2 * t4;
            float* cc = acc[mt][nt];
            #pragma unroll
            for (int half_i = 0; half_i < 2; half_i++) {
                int m = m0 + half_i * 8;
                int bb = m >> 10;
                int tt = m & 1023;
                float v0 = cc[half_i * 2 + 0];
                float v1 = cc[half_i * 2 + 1];
                if constexpr (EPI == 1) {
                    if (n0 < DMODEL) {
                        *reinterpret_cast<uint32_t*>(&g_xinh[(size_t)m * DMODEL + n0]) = pack_h2(v0, v1);
                        g_xinT[((size_t)bb * DMODEL + n0) * LSEQ + tt]     = __float2half_rn(v0);
                        g_xinT[((size_t)bb * DMODEL + n0 + 1) * LSEQ + tt] = __float2half_rn(v1);
                    } else {
                        int dd = n0 - DMODEL;
                        g_zT[((size_t)bb * DMODEL + dd) * LSEQ + tt]     = __float2half_rn(v0);
                        g_zT[((size_t)bb * DMODEL + dd + 1) * LSEQ + tt] = __float2half_rn(v1);
                    }
                } else if constexpr (EPI == 2) {
                    if (n0 < DMODEL) {
                        v0 = softplus_f(v0 + aux[n0]);
                        v1 = softplus_f(v1 + aux[n0 + 1]);
                        g_dtT[((size_t)bb * DMODEL + n0) * LSEQ + tt]     = __float2half_rn(v0);
                        g_dtT[((size_t)bb * DMODEL + n0 + 1) * LSEQ + tt] = __float2half_rn(v1);
                    } else if (n0 < 1040) {
                        int j = n0 - 1024;
                        g_btT[((size_t)bb * NSTATE + j) * LSEQ + tt]     = __float2half_rn(v0);
                        g_btT[((size_t)bb * NSTATE + j + 1) * LSEQ + tt] = __float2half_rn(v1);
                    } else if (n0 < 1056) {
                        int j = n0 - 1040;
                        g_ctT[((size_t)bb * NSTATE + j) * LSEQ + tt]     = __float2half_rn(v0);
                        g_ctT[((size_t)bb * NSTATE + j + 1) * LSEQ + tt] = __float2half_rn(v1);
                    }
                } else { // EPI == 3
                    float2 r = *reinterpret_cast<const float2*>(&aux[(size_t)m * DMODEL + n0]);
                    *reinterpret_cast<float2*>(&O0[(size_t)m * DMODEL + n0]) = make_float2(v0 + r.x, v1 + r.y);
                }
            }
        }
    }
}

// ---------------------------------------------------------------------------
// Sequential SSM scan on time-major fp16 inputs: 8 steps per LDG.128 block,
// double-buffered. Thread = (b, d, n); 16 n-lanes reduce via shfl.
// ---------------------------------------------------------------------------
__global__ __launch_bounds__(256) void scan_kernel(
    const float* __restrict__ A_log,
    const float* __restrict__ h_prev,
    const float* __restrict__ Dvec,
    float* __restrict__ h_out)
{
    int b  = blockIdx.x >> 6;
    int dg = blockIdx.x & 63;
    int n  = threadIdx.x & 15;
    int dl = threadIdx.x >> 4;
    int d  = dg * 16 + dl;

    float Acoef = -__expf(A_log[d * NSTATE + n]);
    float h  = h_prev[((size_t)b * DMODEL + d) * NSTATE + n];
    float Dd = Dvec[d];
    const bool lead = (n == 0);

    const uint4* dtp = reinterpret_cast<const uint4*>(g_dtT  + ((size_t)b * DMODEL + d) * LSEQ);
    const uint4* xip = reinterpret_cast<const uint4*>(g_xinT + ((size_t)b * DMODEL + d) * LSEQ);
    const uint4* ztp = reinterpret_cast<const uint4*>(g_zT   + ((size_t)b * DMODEL + d) * LSEQ);
    const uint4* btp = reinterpret_cast<const uint4*>(g_btT  + ((size_t)b * NSTATE + n) * LSEQ);
    const uint4* ctp = reinterpret_cast<const uint4*>(g_ctT  + ((size_t)b * NSTATE + n) * LSEQ);
    __half* sout = g_ssmh + (size_t)b * LSEQ * DMODEL + d;

    uint4 c_dt = dtp[0];
    uint4 c_xi = xip[0];
    uint4 c_bt = btp[0];
    uint4 c_ct = ctp[0];
    uint4 c_z  = lead ? ztp[0] : make_uint4(0, 0, 0, 0);

    for (int t0 = 0; t0 < LSEQ; t0 += 8) {
        uint4 n_dt, n_xi, n_bt, n_ct, n_z;
        int blk = (t0 >> 3) + 1;
        if (blk < LSEQ / 8) {
            n_dt = dtp[blk];
            n_xi = xip[blk];
            n_bt = btp[blk];
            n_ct = ctp[blk];
            n_z  = lead ? ztp[blk] : make_uint4(0, 0, 0, 0);
        } else {
            n_dt = n_xi = n_bt = n_ct = n_z = make_uint4(0, 0, 0, 0);
        }

        const __half* hd = reinterpret_cast<const __half*>(&c_dt);
        const __half* hx = reinterpret_cast<const __half*>(&c_xi);
        const __half* hb = reinterpret_cast<const __half*>(&c_bt);
        const __half* hc = reinterpret_cast<const __half*>(&c_ct);
        const __half* hz = reinterpret_cast<const __half*>(&c_z);

        #pragma unroll
        for (int j = 0; j < 8; j++) {
            float dtv = __half2float(hd[j]);
            float xin = __half2float(hx[j]);
            float Btv = __half2float(hb[j]);
            float Ctv = __half2float(hc[j]);

            float dA = __expf(dtv * Acoef);
            h = dA * h + (dtv * xin) * Btv;
            float y = h * Ctv;
            y += __shfl_xor_sync(0xffffffffu, y, 1);
            y += __shfl_xor_sync(0xffffffffu, y, 2);
            y += __shfl_xor_sync(0xffffffffu, y, 4);
            y += __shfl_xor_sync(0xffffffffu, y, 8);

            if (lead) {
                float zv = __half2float(hz[j]);
                float sil = zv / (1.f + __expf(-zv));
                sout[(size_t)(t0 + j) * DMODEL] = __float2half_rn(y * sil + xin * Dd);
            }
        }

        c_dt = n_dt; c_xi = n_xi; c_bt = n_bt; c_ct = n_ct; c_z = n_z;
    }
    h_out[((size_t)b * DMODEL + d) * NSTATE + n] = h;
}

// ---------------------------------------------------------------------------
// Launch
// ---------------------------------------------------------------------------
extern "C" void kernel_launch(void* const* d_in, const int* in_sizes, int n_in,
                              void* d_out, int out_size)
{
    const float* x      = (const float*)d_in[0];
    const float* h_prev = (const float*)d_in[1];
    const float* ln_g   = (const float*)d_in[2];
    const float* ln_b   = (const float*)d_in[3];
    const float* W_ig   = (const float*)d_in[4];
    const float* W_dt   = (const float*)d_in[5];
    const float* b_dt   = (const float*)d_in[6];
    const float* A_log  = (const float*)d_in[7];
    const float* W_B    = (const float*)d_in[8];
    const float* W_C    = (const float*)d_in[9];
    const float* Dv     = (const float*)d_in[10];
    const float* W_out  = (const float*)d_in[11];
    float* out = (float*)d_out;

    __half *p_xnormh, *p_xinh, *p_ssmh, *p_wigh, *p_wbch, *p_wouth;
    cudaGetSymbolAddress((void**)&p_xnormh, g_xnormh);
    cudaGetSymbolAddress((void**)&p_xinh,   g_xinh);
    cudaGetSymbolAddress((void**)&p_ssmh,   g_ssmh);
    cudaGetSymbolAddress((void**)&p_wigh,   g_wigh);
    cudaGetSymbolAddress((void**)&p_wbch,   g_wbch);
    cudaGetSymbolAddress((void**)&p_wouth,  g_wouth);

    cudaFuncSetAttribute(gemm_ma<1>, cudaFuncAttributeMaxDynamicSharedMemorySize, SMEM_DYN);
    cudaFuncSetAttribute(gemm_ma<2>, cudaFuncAttributeMaxDynamicSharedMemorySize, SMEM_DYN);
    cudaFuncSetAttribute(gemm_ma<3>, cudaFuncAttributeMaxDynamicSharedMemorySize, SMEM_DYN);

    // 0. weight prep (fp16 conversion + fused W' assembly)
    prep_kernel<<<2048, 256>>>(W_ig, W_dt, W_B, W_C, W_out);

    // 1. LayerNorm (fp16 output)
    layernorm_kernel<<<MTOT, 256>>>(x, ln_g, ln_b);

    // 2. x_proj = x_norm @ W_ig^T -> x_in (row-major fp16 + time-major fp16) | zT
    {
        dim3 grid(N1 / BN, MTOT / BM);
        gemm_ma<1><<<grid, 256, SMEM_DYN>>>(p_xnormh, p_wigh, nullptr, nullptr);
    }

    // 3. fused: dtT = softplus(x_in@W_dt^T + b_dt); btT; ctT  (all time-major)
    {
        dim3 grid(N2 / BN, MTOT / BM);
        gemm_ma<2><<<grid, 256, SMEM_DYN>>>(p_xinh, p_wbch, nullptr, b_dt);
    }

    // 4. scan -> g_ssmh (fp16), h_final -> out tail
    scan_kernel<<<BSZ * 64, 256>>>(A_log, h_prev, Dv, out + XTOT);

    // 5. out = x + ssm @ W_out^T
    {
        dim3 grid(N3 / BN, MTOT / BM);
        gemm_ma<3><<<grid, 256, SMEM_DYN>>>(p_ssmh, p_wouth, out, x);
    }
}

// round 12
// speedup vs baseline: 1.2815x; 1.0866x over previous
#include <cuda_runtime.h>
#include <cuda_fp16.h>
#include <math.h>
#include <stdint.h>

// Problem constants
#define BSZ    8
#define LSEQ   1024
#define DMODEL 1024
#define NSTATE 16
#define MTOT   (BSZ * LSEQ)        // 8192
#define XTOT   (MTOT * DMODEL)     // 8388608
#define KDIM   1024

// GEMM tiling (fp16 m16n8k16)
#define BM 128
#define BN 128
#define BK 32                       // halves per chunk (2 k16 steps)
#define NSTG 4
#define NCHUNK (KDIM / BK)          // 32
#define ROWB 80                     // 64B row + 16B pad (conflict-free, also for ldmatrix)
#define ASTAGE_B (128 * ROWB)       // 10240
#define STAGE_B  (2 * ASTAGE_B)     // 20480
#define SMEM_DYN (NSTG * STAGE_B)   // 81920

// N sizes
#define N1 2048
#define N2 1152                     // 1024 dt + 16 B + 16 C + 96 pad
#define N3 1024

// ---------------------------------------------------------------------------
// Scratch
// ---------------------------------------------------------------------------
__device__ __align__(256) __half g_xnormh[XTOT];        // fp16 (gemm1 A)
__device__ __align__(256) __half g_xinh[XTOT];          // fp16 row-major (gemm2 A)
__device__ __align__(256) __half g_xinT[XTOT];          // fp16 [b][d][t] (scan)
__device__ __align__(256) __half g_zT[XTOT];            // fp16 [b][d][t] (scan)
__device__ __align__(256) __half g_dtT[XTOT];           // fp16 [b][d][t] (scan)
__device__ __align__(256) __half g_btT[MTOT * NSTATE];  // fp16 [b][n][t]
__device__ __align__(256) __half g_ctT[MTOT * NSTATE];  // fp16 [b][n][t]
__device__ __align__(256) __half g_ssmh[XTOT];          // fp16 row-major (gemm3 A)
__device__ __align__(256) __half g_wigh[N1 * KDIM];     // fp16 W_ig
__device__ __align__(256) __half g_wbch[N2 * KDIM];     // fp16 [W_dt;W_B;W_C;0]
__device__ __align__(256) __half g_wouth[N3 * KDIM];    // fp16 W_out

// ---------------------------------------------------------------------------
// Helpers
// ---------------------------------------------------------------------------
__device__ __forceinline__ uint32_t pack_h2(float a, float b) {
    __half2 h = __floats2half2_rn(a, b);
    return *reinterpret_cast<uint32_t*>(&h);
}

__device__ __forceinline__ void mma_f16(float* c, const uint32_t* a, const uint32_t* b) {
    asm volatile(
        "mma.sync.aligned.m16n8k16.row.col.f32.f16.f16.f32 "
        "{%0,%1,%2,%3}, {%4,%5,%6,%7}, {%8,%9}, {%0,%1,%2,%3};"
        : "+f"(c[0]), "+f"(c[1]), "+f"(c[2]), "+f"(c[3])
        : "r"(a[0]), "r"(a[1]), "r"(a[2]), "r"(a[3]), "r"(b[0]), "r"(b[1]));
}

__device__ __forceinline__ void ldmx4(uint32_t& r0, uint32_t& r1, uint32_t& r2,
                                      uint32_t& r3, uint32_t addr) {
    asm volatile("ldmatrix.sync.aligned.m8n8.x4.shared.b16 {%0,%1,%2,%3}, [%4];"
                 : "=r"(r0), "=r"(r1), "=r"(r2), "=r"(r3) : "r"(addr));
}

__device__ __forceinline__ uint32_t smem_u32(const void* p) {
    uint32_t a;
    asm("{ .reg .u64 t; cvta.to.shared.u64 t, %1; cvt.u32.u64 %0, t; }" : "=r"(a) : "l"(p));
    return a;
}
__device__ __forceinline__ void cp16(uint32_t dst, const void* src) {
    asm volatile("cp.async.cg.shared.global [%0], [%1], 16;"
                 :: "r"(dst), "l"(__cvta_generic_to_global(src)));
}
#define CP_COMMIT() asm volatile("cp.async.commit_group;")
#define CP_WAIT2()  asm volatile("cp.async.wait_group 2;" ::: "memory")

__device__ __forceinline__ float softplus_f(float v) {
    return (v > 20.f) ? v : log1pf(expf(v));
}

// ---------------------------------------------------------------------------
// LayerNorm -> fp16 x_norm (only consumer is gemm1's A)
// ---------------------------------------------------------------------------
__global__ __launch_bounds__(256) void layernorm_kernel(
    const float* __restrict__ x,
    const float* __restrict__ g,
    const float* __restrict__ b)
{
    int row = blockIdx.x;
    int t = threadIdx.x;
    float4 v = reinterpret_cast<const float4*>(x + (size_t)row * DMODEL)[t];

    float s  = v.x + v.y + v.z + v.w;
    float sq = v.x * v.x + v.y * v.y + v.z * v.z + v.w * v.w;
    #pragma unroll
    for (int o = 16; o; o >>= 1) {
        s  += __shfl_xor_sync(0xffffffffu, s,  o);
        sq += __shfl_xor_sync(0xffffffffu, sq, o);
    }
    __shared__ float ssum[8], ssq[8], sh_mean, sh_rstd;
    int w = t >> 5;
    if ((t & 31) == 0) { ssum[w] = s; ssq[w] = sq; }
    __syncthreads();
    if (t == 0) {
        float S = 0.f, Q = 0.f;
        #pragma unroll
        for (int i = 0; i < 8; i++) { S += ssum[i]; Q += ssq[i]; }
        float mu  = S * (1.0f / DMODEL);
        float var = Q * (1.0f / DMODEL) - mu * mu;
        sh_mean = mu;
        sh_rstd = rsqrtf(var + 1e-5f);
    }
    __syncthreads();
    float mean = sh_mean, rstd = sh_rstd;

    float4 gg = reinterpret_cast<const float4*>(g)[t];
    float4 bb = reinterpret_cast<const float4*>(b)[t];
    uint2 o;
    o.x = pack_h2((v.x - mean) * rstd * gg.x + bb.x,
                  (v.y - mean) * rstd * gg.y + bb.y);
    o.y = pack_h2((v.z - mean) * rstd * gg.z + bb.z,
                  (v.w - mean) * rstd * gg.w + bb.w);
    reinterpret_cast<uint2*>(g_xnormh + (size_t)row * DMODEL)[t] = o;
}

// ---------------------------------------------------------------------------
// Weight prep: fp16-convert all B operands; assemble fused [W_dt; W_B; W_C; 0]
// ---------------------------------------------------------------------------
__global__ __launch_bounds__(256) void prep_kernel(
    const float* __restrict__ W_ig,
    const float* __restrict__ W_dt,
    const float* __restrict__ W_B,
    const float* __restrict__ W_C,
    const float* __restrict__ W_out)
{
    const int K4 = KDIM / 4;
    int stride = gridDim.x * blockDim.x;
    const int nig  = N1 * K4;
    const int nbc  = 1056 * K4;
    const int nout = N3 * K4;
    int total = nig + nbc + nout;
    for (int i = blockIdx.x * blockDim.x + threadIdx.x; i < total; i += stride) {
        const float4* src;
        __half* dst;
        if (i < nig) {
            src = reinterpret_cast<const float4*>(W_ig) + i;
            dst = g_wigh + (size_t)i * 4;
        } else if (i < nig + nbc) {
            int j = i - nig;
            int row = j / K4;
            int c4  = j % K4;
            const float* s;
            if (row < 1024)      s = W_dt + (size_t)row * KDIM;
            else if (row < 1040) s = W_B + (size_t)(row - 1024) * KDIM;
            else                 s = W_C + (size_t)(row - 1040) * KDIM;
            src = reinterpret_cast<const float4*>(s) + c4;
            dst = g_wbch + (size_t)j * 4;
        } else {
            int j = i - nig - nbc;
            src = reinterpret_cast<const float4*>(W_out) + j;
            dst = g_wouth + (size_t)j * 4;
        }
        float4 v = *src;
        uint2 o;
        o.x = pack_h2(v.x, v.y);
        o.y = pack_h2(v.z, v.w);
        *reinterpret_cast<uint2*>(dst) = o;
    }
}

// ---------------------------------------------------------------------------
// FP16 mma.sync m16n8k16 GEMM, cp.async 4-stage pipeline, ldmatrix fragments.
// Tile 128x128, 8 warps (2m x 4n), warp 64x32.
// EPI 1: n<1024 -> g_xinh (row-major) + g_xinT (time-major); else g_zT
// EPI 2: n<1024 -> softplus(v+aux[n]) -> g_dtT; 1024-1039 -> g_btT;
//        1040-1055 -> g_ctT; else discard
// EPI 3: O0 = v + aux[m*1024+n]  (fp32 row-major)
// ---------------------------------------------------------------------------
template<int EPI>
__global__ __launch_bounds__(256, 2) void gemm_ma(
    const __half* __restrict__ A,
    const __half* __restrict__ Bw,
    float* __restrict__ O0,
    const float* __restrict__ aux)
{
    extern __shared__ char dsm[];
    const uint32_t dsm_addr = smem_u32(dsm);

    const int tid  = threadIdx.x;
    const int wid  = tid >> 5;
    const int lane = tid & 31;
    const int bm   = blockIdx.y * BM;
    const int bn   = blockIdx.x * BN;
    const int wm   = wid >> 2;
    const int wn   = wid & 3;
    const int g    = lane >> 2;
    const int t4   = lane & 3;

    const __half* Ag = A  + (size_t)bm * KDIM;
    const __half* Bg = Bw + (size_t)bn * KDIM;

    const int lrow = tid >> 2;      // 0..63 (+it*64)
    const int lc16 = tid & 3;       // 16B column 0..3

    auto load_chunk = [&](int c, int stg) {
        uint32_t base = dsm_addr + (uint32_t)(stg * STAGE_B);
        #pragma unroll
        for (int it = 0; it < 2; it++) {
            int row = lrow + it * 64;
            cp16(base + (uint32_t)(row * ROWB + lc16 * 16),
                 Ag + (size_t)row * KDIM + c * BK + lc16 * 8);
        }
        uint32_t baseB = base + ASTAGE_B;
        #pragma unroll
        for (int it = 0; it < 2; it++) {
            int row = lrow + it * 64;
            cp16(baseB + (uint32_t)(row * ROWB + lc16 * 16),
                 Bg + (size_t)row * KDIM + c * BK + lc16 * 8);
        }
    };

    // ldmatrix per-lane row/offset patterns
    const int rowA  = (lane & 7) + ((lane >> 3) & 1) * 8;  // A: m within 16
    const int koffA = (lane >> 4) * 16;                    // A: k-half select
    const int rowB  = (lane & 7) + (lane >> 4) * 8;        // B: n within 16
    const int koffB = ((lane >> 3) & 1) * 16;              // B: k-half select

    float acc[4][4][4];
    #pragma unroll
    for (int i = 0; i < 4; i++)
        #pragma unroll
        for (int j = 0; j < 4; j++)
            #pragma unroll
            for (int r = 0; r < 4; r++) acc[i][j][r] = 0.f;

    // prologue: chunks 0,1,2
    load_chunk(0, 0); CP_COMMIT();
    load_chunk(1, 1); CP_COMMIT();
    load_chunk(2, 2); CP_COMMIT();

    for (int c = 0; c < NCHUNK; c++) {
        CP_WAIT2();
        __syncthreads();

        if (c + 3 < NCHUNK) { load_chunk(c + 3, (c + 3) & (NSTG - 1)); CP_COMMIT(); }

        uint32_t sbase = dsm_addr + (uint32_t)((c & (NSTG - 1)) * STAGE_B);
        uint32_t aAddr = sbase + (uint32_t)((wm * 64 + rowA) * ROWB + koffA);
        uint32_t bAddr = sbase + ASTAGE_B + (uint32_t)((wn * 32 + rowB) * ROWB + koffB);

        #pragma unroll
        for (int s = 0; s < 2; s++) {
            const int ko = s * 32;   // byte offset of this k16 step
            uint32_t bf[4][2];
            #pragma unroll
            for (int np = 0; np < 2; np++)
                ldmx4(bf[2 * np][0], bf[2 * np][1], bf[2 * np + 1][0], bf[2 * np + 1][1],
                      bAddr + (uint32_t)(np * 16 * ROWB + ko));
            #pragma unroll
            for (int mt = 0; mt < 4; mt++) {
                uint32_t af[4];
                ldmx4(af[0], af[1], af[2], af[3],
                      aAddr + (uint32_t)(mt * 16 * ROWB + ko));
                #pragma unroll
                for (int nt = 0; nt < 4; nt++)
                    mma_f16(acc[mt][nt], af, bf[nt]);
            }
        }
    }

    // Epilogue
    #pragma unroll
    for (int mt = 0; mt < 4; mt++) {
        #pragma unroll
        for (int nt = 0; nt < 4; nt++) {
            int m0 = bm + wm * 64 + mt * 16 + g;
            int n0 = bn + wn * 32 + nt * 8 + 2 * t4;
            float* cc = acc[mt][nt];
            #pragma unroll
            for (int half_i = 0; half_i < 2; half_i++) {
                int m = m0 + half_i * 8;
                int bb = m >> 10;
                int tt = m & 1023;
                float v0 = cc[half_i * 2 + 0];
                float v1 = cc[half_i * 2 + 1];
                if constexpr (EPI == 1) {
                    if (n0 < DMODEL) {
                        *reinterpret_cast<uint32_t*>(&g_xinh[(size_t)m * DMODEL + n0]) = pack_h2(v0, v1);
                        g_xinT[((size_t)bb * DMODEL + n0) * LSEQ + tt]     = __float2half_rn(v0);
                        g_xinT[((size_t)bb * DMODEL + n0 + 1) * LSEQ + tt] = __float2half_rn(v1);
                    } else {
                        int dd = n0 - DMODEL;
                        g_zT[((size_t)bb * DMODEL + dd) * LSEQ + tt]     = __float2half_rn(v0);
                        g_zT[((size_t)bb * DMODEL + dd + 1) * LSEQ + tt] = __float2half_rn(v1);
                    }
                } else if constexpr (EPI == 2) {
                    if (n0 < DMODEL) {
                        v0 = softplus_f(v0 + aux[n0]);
                        v1 = softplus_f(v1 + aux[n0 + 1]);
                        g_dtT[((size_t)bb * DMODEL + n0) * LSEQ + tt]     = __float2half_rn(v0);
                        g_dtT[((size_t)bb * DMODEL + n0 + 1) * LSEQ + tt] = __float2half_rn(v1);
                    } else if (n0 < 1040) {
                        int j = n0 - 1024;
                        g_btT[((size_t)bb * NSTATE + j) * LSEQ + tt]     = __float2half_rn(v0);
                        g_btT[((size_t)bb * NSTATE + j + 1) * LSEQ + tt] = __float2half_rn(v1);
                    } else if (n0 < 1056) {
                        int j = n0 - 1040;
                        g_ctT[((size_t)bb * NSTATE + j) * LSEQ + tt]     = __float2half_rn(v0);
                        g_ctT[((size_t)bb * NSTATE + j + 1) * LSEQ + tt] = __float2half_rn(v1);
                    }
                } else { // EPI == 3
                    float2 r = *reinterpret_cast<const float2*>(&aux[(size_t)m * DMODEL + n0]);
                    *reinterpret_cast<float2*>(&O0[(size_t)m * DMODEL + n0]) = make_float2(v0 + r.x, v1 + r.y);
                }
            }
        }
    }
}

// ---------------------------------------------------------------------------
// Sequential SSM scan, time-major fp16 inputs.
// bt/ct staged through SMEM per 256-step chunk (coalesced; kills the 2KB-
// strided 32-wavefront scattered LDGs). dt/xi/z stay global (lane-uniform,
// broadcast) with 8-step double buffering.
// ---------------------------------------------------------------------------
#define TCH 256
__global__ __launch_bounds__(256) void scan_kernel(
    const float* __restrict__ A_log,
    const float* __restrict__ h_prev,
    const float* __restrict__ Dvec,
    float* __restrict__ h_out)
{
    __shared__ __half sbt[16][TCH + 8];
    __shared__ __half sct[16][TCH + 8];

    int tid = threadIdx.x;
    int b  = blockIdx.x >> 6;
    int dg = blockIdx.x & 63;
    int n  = tid & 15;
    int dl = tid >> 4;
    int d  = dg * 16 + dl;

    float Acoef = -__expf(A_log[d * NSTATE + n]);
    float h  = h_prev[((size_t)b * DMODEL + d) * NSTATE + n];
    float Dd = Dvec[d];
    const bool lead = (n == 0);

    const uint4* dtp = reinterpret_cast<const uint4*>(g_dtT  + ((size_t)b * DMODEL + d) * LSEQ);
    const uint4* xip = reinterpret_cast<const uint4*>(g_xinT + ((size_t)b * DMODEL + d) * LSEQ);
    const uint4* ztp = reinterpret_cast<const uint4*>(g_zT   + ((size_t)b * DMODEL + d) * LSEQ);
    const __half* btg = g_btT + (size_t)b * NSTATE * LSEQ;
    const __half* ctg = g_ctT + (size_t)b * NSTATE * LSEQ;
    __half* sout = g_ssmh + (size_t)b * LSEQ * DMODEL + d;

    uint4 c_dt = dtp[0];
    uint4 c_xi = xip[0];
    uint4 c_z  = lead ? ztp[0] : make_uint4(0, 0, 0, 0);

    for (int tc = 0; tc < LSEQ; tc += TCH) {
        __syncthreads();   // all reads of previous chunk's tiles done
        #pragma unroll
        for (int it = 0; it < 2; it++) {
            int i = tid + it * 256;
            int row = i >> 5;          // 0..15
            int col = i & 31;          // uint4 column
            *reinterpret_cast<uint4*>(&sbt[row][col * 8]) =
                *reinterpret_cast<const uint4*>(btg + (size_t)row * LSEQ + tc + col * 8);
            *reinterpret_cast<uint4*>(&sct[row][col * 8]) =
                *reinterpret_cast<const uint4*>(ctg + (size_t)row * LSEQ + tc + col * 8);
        }
        __syncthreads();

        for (int t0 = 0; t0 < TCH; t0 += 8) {
            int gblk = (tc + t0) >> 3;
            uint4 n_dt, n_xi, n_z;
            if (gblk + 1 < LSEQ / 8) {
                n_dt = dtp[gblk + 1];
                n_xi = xip[gblk + 1];
                n_z  = lead ? ztp[gblk + 1] : make_uint4(0, 0, 0, 0);
            } else {
                n_dt = n_xi = n_z = make_uint4(0, 0, 0, 0);
            }

            uint4 c_bt = *reinterpret_cast<const uint4*>(&sbt[n][t0]);
            uint4 c_ct = *reinterpret_cast<const uint4*>(&sct[n][t0]);

            const __half* hd = reinterpret_cast<const __half*>(&c_dt);
            const __half* hx = reinterpret_cast<const __half*>(&c_xi);
            const __half* hb = reinterpret_cast<const __half*>(&c_bt);
            const __half* hc = reinterpret_cast<const __half*>(&c_ct);
            const __half* hz = reinterpret_cast<const __half*>(&c_z);

            #pragma unroll
            for (int j = 0; j < 8; j++) {
                float dtv = __half2float(hd[j]);
                float xin = __half2float(hx[j]);
                float Btv = __half2float(hb[j]);
                float Ctv = __half2float(hc[j]);

                float dA = __expf(dtv * Acoef);
                h = dA * h + (dtv * xin) * Btv;
                float y = h * Ctv;
                y += __shfl_xor_sync(0xffffffffu, y, 1);
                y += __shfl_xor_sync(0xffffffffu, y, 2);
                y += __shfl_xor_sync(0xffffffffu, y, 4);
                y += __shfl_xor_sync(0xffffffffu, y, 8);

                if (lead) {
                    float zv = __half2float(hz[j]);
                    float sil = zv / (1.f + __expf(-zv));
                    sout[(size_t)(tc + t0 + j) * DMODEL] = __float2half_rn(y * sil + xin * Dd);
                }
            }

            c_dt = n_dt; c_xi = n_xi; c_z = n_z;
        }
    }
    h_out[((size_t)b * DMODEL + d) * NSTATE + n] = h;
}

// ---------------------------------------------------------------------------
// Launch
// ---------------------------------------------------------------------------
extern "C" void kernel_launch(void* const* d_in, const int* in_sizes, int n_in,
                              void* d_out, int out_size)
{
    const float* x      = (const float*)d_in[0];
    const float* h_prev = (const float*)d_in[1];
    const float* ln_g   = (const float*)d_in[2];
    const float* ln_b   = (const float*)d_in[3];
    const float* W_ig   = (const float*)d_in[4];
    const float* W_dt   = (const float*)d_in[5];
    const float* b_dt   = (const float*)d_in[6];
    const float* A_log  = (const float*)d_in[7];
    const float* W_B    = (const float*)d_in[8];
    const float* W_C    = (const float*)d_in[9];
    const float* Dv     = (const float*)d_in[10];
    const float* W_out  = (const float*)d_in[11];
    float* out = (float*)d_out;

    __half *p_xnormh, *p_xinh, *p_ssmh, *p_wigh, *p_wbch, *p_wouth;
    cudaGetSymbolAddress((void**)&p_xnormh, g_xnormh);
    cudaGetSymbolAddress((void**)&p_xinh,   g_xinh);
    cudaGetSymbolAddress((void**)&p_ssmh,   g_ssmh);
    cudaGetSymbolAddress((void**)&p_wigh,   g_wigh);
    cudaGetSymbolAddress((void**)&p_wbch,   g_wbch);
    cudaGetSymbolAddress((void**)&p_wouth,  g_wouth);

    cudaFuncSetAttribute(gemm_ma<1>, cudaFuncAttributeMaxDynamicSharedMemorySize, SMEM_DYN);
    cudaFuncSetAttribute(gemm_ma<2>, cudaFuncAttributeMaxDynamicSharedMemorySize, SMEM_DYN);
    cudaFuncSetAttribute(gemm_ma<3>, cudaFuncAttributeMaxDynamicSharedMemorySize, SMEM_DYN);

    // 0. weight prep (fp16 conversion + fused W' assembly)
    prep_kernel<<<2048, 256>>>(W_ig, W_dt, W_B, W_C, W_out);

    // 1. LayerNorm (fp16 output)
    layernorm_kernel<<<MTOT, 256>>>(x, ln_g, ln_b);

    // 2. x_proj = x_norm @ W_ig^T -> x_in (row-major fp16 + time-major fp16) | zT
    {
        dim3 grid(N1 / BN, MTOT / BM);
        gemm_ma<1><<<grid, 256, SMEM_DYN>>>(p_xnormh, p_wigh, nullptr, nullptr);
    }

    // 3. fused: dtT = softplus(x_in@W_dt^T + b_dt); btT; ctT  (all time-major)
    {
        dim3 grid(N2 / BN, MTOT / BM);
        gemm_ma<2><<<grid, 256, SMEM_DYN>>>(p_xinh, p_wbch, nullptr, b_dt);
    }

    // 4. scan -> g_ssmh (fp16), h_final -> out tail
    scan_kernel<<<BSZ * 64, 256>>>(A_log, h_prev, Dv, out + XTOT);

    // 5. out = x + ssm @ W_out^T
    {
        dim3 grid(N3 / BN, MTOT / BM);
        gemm_ma<3><<<grid, 256, SMEM_DYN>>>(p_ssmh, p_wouth, out, x);
    }
}

// round 13
// speedup vs baseline: 1.6480x; 1.2860x over previous
#include <cuda_runtime.h>
#include <cuda_fp16.h>
#include <math.h>
#include <stdint.h>

// Problem constants
#define BSZ    8
#define LSEQ   1024
#define DMODEL 1024
#define NSTATE 16
#define MTOT   (BSZ * LSEQ)        // 8192
#define XTOT   (MTOT * DMODEL)     // 8388608
#define KDIM   1024

// GEMM tiling (fp16 m16n8k16)
#define BM 128
#define BN 128
#define BK 32                       // halves per chunk (2 k16 steps)
#define NSTG 4
#define NCHUNK (KDIM / BK)          // 32
#define ROWB 80                     // 64B row + 16B pad (conflict-free, also for ldmatrix)
#define ASTAGE_B (128 * ROWB)       // 10240
#define STAGE_B  (2 * ASTAGE_B)     // 20480
#define SMEM_DYN (NSTG * STAGE_B)   // 81920

// N sizes
#define N1 2048
#define N2 1152                     // 1024 dt + 16 B + 16 C + 96 pad
#define N3 1024

// ---------------------------------------------------------------------------
// Scratch
// ---------------------------------------------------------------------------
__device__ __align__(256) __half g_xnormh[XTOT];        // fp16 (gemm1 A)
__device__ __align__(256) __half g_xinh[XTOT];          // fp16 row-major (gemm2 A)
__device__ __align__(256) __half g_xinT[XTOT];          // fp16 [b][d][t] (scan)
__device__ __align__(256) __half g_zT[XTOT];            // fp16 [b][d][t] (scan)
__device__ __align__(256) __half g_dtT[XTOT];           // fp16 [b][d][t] (scan)
__device__ __align__(256) __half g_btT[MTOT * NSTATE];  // fp16 [b][n][t]
__device__ __align__(256) __half g_ctT[MTOT * NSTATE];  // fp16 [b][n][t]
__device__ __align__(256) __half g_ssmh[XTOT];          // fp16 row-major (gemm3 A)
__device__ __align__(256) __half g_wigh[N1 * KDIM];     // fp16 W_ig
__device__ __align__(256) __half g_wbch[N2 * KDIM];     // fp16 [W_dt;W_B;W_C;0]
__device__ __align__(256) __half g_wouth[N3 * KDIM];    // fp16 W_out

// ---------------------------------------------------------------------------
// Helpers
// ---------------------------------------------------------------------------
__device__ __forceinline__ uint32_t pack_h2(float a, float b) {
    __half2 h = __floats2half2_rn(a, b);
    return *reinterpret_cast<uint32_t*>(&h);
}

__device__ __forceinline__ void mma_f16(float* c, const uint32_t* a, const uint32_t* b) {
    asm volatile(
        "mma.sync.aligned.m16n8k16.row.col.f32.f16.f16.f32 "
        "{%0,%1,%2,%3}, {%4,%5,%6,%7}, {%8,%9}, {%0,%1,%2,%3};"
        : "+f"(c[0]), "+f"(c[1]), "+f"(c[2]), "+f"(c[3])
        : "r"(a[0]), "r"(a[1]), "r"(a[2]), "r"(a[3]), "r"(b[0]), "r"(b[1]));
}

__device__ __forceinline__ void ldmx4(uint32_t& r0, uint32_t& r1, uint32_t& r2,
                                      uint32_t& r3, uint32_t addr) {
    asm volatile("ldmatrix.sync.aligned.m8n8.x4.shared.b16 {%0,%1,%2,%3}, [%4];"
                 : "=r"(r0), "=r"(r1), "=r"(r2), "=r"(r3) : "r"(addr));
}

__device__ __forceinline__ uint32_t smem_u32(const void* p) {
    uint32_t a;
    asm("{ .reg .u64 t; cvta.to.shared.u64 t, %1; cvt.u32.u64 %0, t; }" : "=r"(a) : "l"(p));
    return a;
}
__device__ __forceinline__ void cp16(uint32_t dst, const void* src) {
    asm volatile("cp.async.cg.shared.global [%0], [%1], 16;"
                 :: "r"(dst), "l"(__cvta_generic_to_global(src)));
}
#define CP_COMMIT() asm volatile("cp.async.commit_group;")
#define CP_WAIT2()  asm volatile("cp.async.wait_group 2;" ::: "memory")

__device__ __forceinline__ float softplus_f(float v) {
    return (v > 20.f) ? v : log1pf(expf(v));
}

// ---------------------------------------------------------------------------
// LayerNorm -> fp16 x_norm (only consumer is gemm1's A)
// ---------------------------------------------------------------------------
__global__ __launch_bounds__(256) void layernorm_kernel(
    const float* __restrict__ x,
    const float* __restrict__ g,
    const float* __restrict__ b)
{
    int row = blockIdx.x;
    int t = threadIdx.x;
    float4 v = reinterpret_cast<const float4*>(x + (size_t)row * DMODEL)[t];

    float s  = v.x + v.y + v.z + v.w;
    float sq = v.x * v.x + v.y * v.y + v.z * v.z + v.w * v.w;
    #pragma unroll
    for (int o = 16; o; o >>= 1) {
        s  += __shfl_xor_sync(0xffffffffu, s,  o);
        sq += __shfl_xor_sync(0xffffffffu, sq, o);
    }
    __shared__ float ssum[8], ssq[8], sh_mean, sh_rstd;
    int w = t >> 5;
    if ((t & 31) == 0) { ssum[w] = s; ssq[w] = sq; }
    __syncthreads();
    if (t == 0) {
        float S = 0.f, Q = 0.f;
        #pragma unroll
        for (int i = 0; i < 8; i++) { S += ssum[i]; Q += ssq[i]; }
        float mu  = S * (1.0f / DMODEL);
        float var = Q * (1.0f / DMODEL) - mu * mu;
        sh_mean = mu;
        sh_rstd = rsqrtf(var + 1e-5f);
    }
    __syncthreads();
    float mean = sh_mean, rstd = sh_rstd;

    float4 gg = reinterpret_cast<const float4*>(g)[t];
    float4 bb = reinterpret_cast<const float4*>(b)[t];
    uint2 o;
    o.x = pack_h2((v.x - mean) * rstd * gg.x + bb.x,
                  (v.y - mean) * rstd * gg.y + bb.y);
    o.y = pack_h2((v.z - mean) * rstd * gg.z + bb.z,
                  (v.w - mean) * rstd * gg.w + bb.w);
    reinterpret_cast<uint2*>(g_xnormh + (size_t)row * DMODEL)[t] = o;
}

// ---------------------------------------------------------------------------
// Weight prep: fp16-convert all B operands; assemble fused [W_dt; W_B; W_C; 0]
// ---------------------------------------------------------------------------
__global__ __launch_bounds__(256) void prep_kernel(
    const float* __restrict__ W_ig,
    const float* __restrict__ W_dt,
    const float* __restrict__ W_B,
    const float* __restrict__ W_C,
    const float* __restrict__ W_out)
{
    const int K4 = KDIM / 4;
    int stride = gridDim.x * blockDim.x;
    const int nig  = N1 * K4;
    const int nbc  = 1056 * K4;
    const int nout = N3 * K4;
    int total = nig + nbc + nout;
    for (int i = blockIdx.x * blockDim.x + threadIdx.x; i < total; i += stride) {
        const float4* src;
        __half* dst;
        if (i < nig) {
            src = reinterpret_cast<const float4*>(W_ig) + i;
            dst = g_wigh + (size_t)i * 4;
        } else if (i < nig + nbc) {
            int j = i - nig;
            int row = j / K4;
            int c4  = j % K4;
            const float* s;
            if (row < 1024)      s = W_dt + (size_t)row * KDIM;
            else if (row < 1040) s = W_B + (size_t)(row - 1024) * KDIM;
            else                 s = W_C + (size_t)(row - 1040) * KDIM;
            src = reinterpret_cast<const float4*>(s) + c4;
            dst = g_wbch + (size_t)j * 4;
        } else {
            int j = i - nig - nbc;
            src = reinterpret_cast<const float4*>(W_out) + j;
            dst = g_wouth + (size_t)j * 4;
        }
        float4 v = *src;
        uint2 o;
        o.x = pack_h2(v.x, v.y);
        o.y = pack_h2(v.z, v.w);
        *reinterpret_cast<uint2*>(dst) = o;
    }
}

// ---------------------------------------------------------------------------
// FP16 mma.sync m16n8k16 GEMM, cp.async 4-stage pipeline, ldmatrix fragments.
// Tile 128x128, 8 warps (2m x 4n), warp 64x32.
// EPI 1: n<1024 -> g_xinh (row-major) + g_xinT (time-major); else g_zT
// EPI 2: n<1024 -> softplus(v+aux[n]) -> g_dtT; 1024-1039 -> g_btT;
//        1040-1055 -> g_ctT; else discard
// EPI 3: O0 = v + aux[m*1024+n]  (fp32 row-major)
// ---------------------------------------------------------------------------
template<int EPI>
__global__ __launch_bounds__(256, 2) void gemm_ma(
    const __half* __restrict__ A,
    const __half* __restrict__ Bw,
    float* __restrict__ O0,
    const float* __restrict__ aux)
{
    extern __shared__ char dsm[];
    const uint32_t dsm_addr = smem_u32(dsm);

    const int tid  = threadIdx.x;
    const int wid  = tid >> 5;
    const int lane = tid & 31;
    const int bm   = blockIdx.y * BM;
    const int bn   = blockIdx.x * BN;
    const int wm   = wid >> 2;
    const int wn   = wid & 3;
    const int g    = lane >> 2;
    const int t4   = lane & 3;

    const __half* Ag = A  + (size_t)bm * KDIM;
    const __half* Bg = Bw + (size_t)bn * KDIM;

    const int lrow = tid >> 2;      // 0..63 (+it*64)
    const int lc16 = tid & 3;       // 16B column 0..3

    auto load_chunk = [&](int c, int stg) {
        uint32_t base = dsm_addr + (uint32_t)(stg * STAGE_B);
        #pragma unroll
        for (int it = 0; it < 2; it++) {
            int row = lrow + it * 64;
            cp16(base + (uint32_t)(row * ROWB + lc16 * 16),
                 Ag + (size_t)row * KDIM + c * BK + lc16 * 8);
        }
        uint32_t baseB = base + ASTAGE_B;
        #pragma unroll
        for (int it = 0; it < 2; it++) {
            int row = lrow + it * 64;
            cp16(baseB + (uint32_t)(row * ROWB + lc16 * 16),
                 Bg + (size_t)row * KDIM + c * BK + lc16 * 8);
        }
    };

    // ldmatrix per-lane row/offset patterns
    const int rowA  = (lane & 7) + ((lane >> 3) & 1) * 8;  // A: m within 16
    const int koffA = (lane >> 4) * 16;                    // A: k-half select
    const int rowB  = (lane & 7) + (lane >> 4) * 8;        // B: n within 16
    const int koffB = ((lane >> 3) & 1) * 16;              // B: k-half select

    float acc[4][4][4];
    #pragma unroll
    for (int i = 0; i < 4; i++)
        #pragma unroll
        for (int j = 0; j < 4; j++)
            #pragma unroll
            for (int r = 0; r < 4; r++) acc[i][j][r] = 0.f;

    // prologue: chunks 0,1,2
    load_chunk(0, 0); CP_COMMIT();
    load_chunk(1, 1); CP_COMMIT();
    load_chunk(2, 2); CP_COMMIT();

    for (int c = 0; c < NCHUNK; c++) {
        CP_WAIT2();
        __syncthreads();

        if (c + 3 < NCHUNK) { load_chunk(c + 3, (c + 3) & (NSTG - 1)); CP_COMMIT(); }

        uint32_t sbase = dsm_addr + (uint32_t)((c & (NSTG - 1)) * STAGE_B);
        uint32_t aAddr = sbase + (uint32_t)((wm * 64 + rowA) * ROWB + koffA);
        uint32_t bAddr = sbase + ASTAGE_B + (uint32_t)((wn * 32 + rowB) * ROWB + koffB);

        #pragma unroll
        for (int s = 0; s < 2; s++) {
            const int ko = s * 32;   // byte offset of this k16 step
            uint32_t bf[4][2];
            #pragma unroll
            for (int np = 0; np < 2; np++)
                ldmx4(bf[2 * np][0], bf[2 * np][1], bf[2 * np + 1][0], bf[2 * np + 1][1],
                      bAddr + (uint32_t)(np * 16 * ROWB + ko));
            #pragma unroll
            for (int mt = 0; mt < 4; mt++) {
                uint32_t af[4];
                ldmx4(af[0], af[1], af[2], af[3],
                      aAddr + (uint32_t)(mt * 16 * ROWB + ko));
                #pragma unroll
                for (int nt = 0; nt < 4; nt++)
                    mma_f16(acc[mt][nt], af, bf[nt]);
            }
        }
    }

    // Epilogue
    #pragma unroll
    for (int mt = 0; mt < 4; mt++) {
        #pragma unroll
        for (int nt = 0; nt < 4; nt++) {
            int m0 = bm + wm * 64 + mt * 16 + g;
            int n0 = bn + wn * 32 + nt * 8 + 2 * t4;
            float* cc = acc[mt][nt];
            #pragma unroll
            for (int half_i = 0; half_i < 2; half_i++) {
                int m = m0 + half_i * 8;
                int bb = m >> 10;
                int tt = m & 1023;
                float v0 = cc[half_i * 2 + 0];
                float v1 = cc[half_i * 2 + 1];
                if constexpr (EPI == 1) {
                    if (n0 < DMODEL) {
                        *reinterpret_cast<uint32_t*>(&g_xinh[(size_t)m * DMODEL + n0]) = pack_h2(v0, v1);
                        g_xinT[((size_t)bb * DMODEL + n0) * LSEQ + tt]     = __float2half_rn(v0);
                        g_xinT[((size_t)bb * DMODEL + n0 + 1) * LSEQ + tt] = __float2half_rn(v1);
                    } else {
                        int dd = n0 - DMODEL;
                        g_zT[((size_t)bb * DMODEL + dd) * LSEQ + tt]     = __float2half_rn(v0);
                        g_zT[((size_t)bb * DMODEL + dd + 1) * LSEQ + tt] = __float2half_rn(v1);
                    }
                } else if constexpr (EPI == 2) {
                    if (n0 < DMODEL) {
                        v0 = softplus_f(v0 + aux[n0]);
                        v1 = softplus_f(v1 + aux[n0 + 1]);
                        g_dtT[((size_t)bb * DMODEL + n0) * LSEQ + tt]     = __float2half_rn(v0);
                        g_dtT[((size_t)bb * DMODEL + n0 + 1) * LSEQ + tt] = __float2half_rn(v1);
                    } else if (n0 < 1040) {
                        int j = n0 - 1024;
                        g_btT[((size_t)bb * NSTATE + j) * LSEQ + tt]     = __float2half_rn(v0);
                        g_btT[((size_t)bb * NSTATE + j + 1) * LSEQ + tt] = __float2half_rn(v1);
                    } else if (n0 < 1056) {
                        int j = n0 - 1040;
                        g_ctT[((size_t)bb * NSTATE + j) * LSEQ + tt]     = __float2half_rn(v0);
                        g_ctT[((size_t)bb * NSTATE + j + 1) * LSEQ + tt] = __float2half_rn(v1);
                    }
                } else { // EPI == 3
                    float2 r = *reinterpret_cast<const float2*>(&aux[(size_t)m * DMODEL + n0]);
                    *reinterpret_cast<float2*>(&O0[(size_t)m * DMODEL + n0]) = make_float2(v0 + r.x, v1 + r.y);
                }
            }
        }
    }
}

// ---------------------------------------------------------------------------
// Sequential SSM scan, time-major fp16 inputs, bt/ct staged through SMEM.
// R13: phase-restructured 8-step block for explicit cross-step ILP:
//   batch cvt -> batch exp -> 8-FMA h chain -> round-interleaved shfls ->
//   lead epilogue. Arithmetic order on h identical to R12 (bitwise same).
// ---------------------------------------------------------------------------
#define TCH 256
__global__ __launch_bounds__(256, 3) void scan_kernel(
    const float* __restrict__ A_log,
    const float* __restrict__ h_prev,
    const float* __restrict__ Dvec,
    float* __restrict__ h_out)
{
    __shared__ __half sbt[16][TCH + 8];
    __shared__ __half sct[16][TCH + 8];

    int tid = threadIdx.x;
    int b  = blockIdx.x >> 6;
    int dg = blockIdx.x & 63;
    int n  = tid & 15;
    int dl = tid >> 4;
    int d  = dg * 16 + dl;

    float Acoef = -__expf(A_log[d * NSTATE + n]);
    float h  = h_prev[((size_t)b * DMODEL + d) * NSTATE + n];
    float Dd = Dvec[d];
    const bool lead = (n == 0);

    const uint4* dtp = reinterpret_cast<const uint4*>(g_dtT  + ((size_t)b * DMODEL + d) * LSEQ);
    const uint4* xip = reinterpret_cast<const uint4*>(g_xinT + ((size_t)b * DMODEL + d) * LSEQ);
    const uint4* ztp = reinterpret_cast<const uint4*>(g_zT   + ((size_t)b * DMODEL + d) * LSEQ);
    const __half* btg = g_btT + (size_t)b * NSTATE * LSEQ;
    const __half* ctg = g_ctT + (size_t)b * NSTATE * LSEQ;
    __half* sout = g_ssmh + (size_t)b * LSEQ * DMODEL + d;

    uint4 c_dt = dtp[0];
    uint4 c_xi = xip[0];
    uint4 c_z  = lead ? ztp[0] : make_uint4(0, 0, 0, 0);

    for (int tc = 0; tc < LSEQ; tc += TCH) {
        __syncthreads();   // all reads of previous chunk's tiles done
        #pragma unroll
        for (int it = 0; it < 2; it++) {
            int i = tid + it * 256;
            int row = i >> 5;          // 0..15
            int col = i & 31;          // uint4 column
            *reinterpret_cast<uint4*>(&sbt[row][col * 8]) =
                *reinterpret_cast<const uint4*>(btg + (size_t)row * LSEQ + tc + col * 8);
            *reinterpret_cast<uint4*>(&sct[row][col * 8]) =
                *reinterpret_cast<const uint4*>(ctg + (size_t)row * LSEQ + tc + col * 8);
        }
        __syncthreads();

        for (int t0 = 0; t0 < TCH; t0 += 8) {
            int gblk = (tc + t0) >> 3;
            uint4 n_dt, n_xi, n_z;
            if (gblk + 1 < LSEQ / 8) {
                n_dt = dtp[gblk + 1];
                n_xi = xip[gblk + 1];
                n_z  = lead ? ztp[gblk + 1] : make_uint4(0, 0, 0, 0);
            } else {
                n_dt = n_xi = n_z = make_uint4(0, 0, 0, 0);
            }

            uint4 c_bt = *reinterpret_cast<const uint4*>(&sbt[n][t0]);
            uint4 c_ct = *reinterpret_cast<const uint4*>(&sct[n][t0]);

            const __half2* pd = reinterpret_cast<const __half2*>(&c_dt);
            const __half2* px = reinterpret_cast<const __half2*>(&c_xi);
            const __half2* pb = reinterpret_cast<const __half2*>(&c_bt);
            const __half2* pc = reinterpret_cast<const __half2*>(&c_ct);

            // phase 1: batch convert + u = (dt*xi)*bt, ct stash
            float dt8[8], u8[8], ct8[8];
            #pragma unroll
            for (int p = 0; p < 4; p++) {
                float2 fd = __half22float2(pd[p]);
                float2 fx = __half22float2(px[p]);
                float2 fb = __half22float2(pb[p]);
                float2 fc = __half22float2(pc[p]);
                dt8[2 * p]     = fd.x;  dt8[2 * p + 1] = fd.y;
                u8[2 * p]      = (fd.x * fx.x) * fb.x;
                u8[2 * p + 1]  = (fd.y * fx.y) * fb.y;
                ct8[2 * p]     = fc.x;  ct8[2 * p + 1] = fc.y;
            }

            // phase 2: batch exp (MUFU pipelined, independent of h)
            float dA8[8];
            #pragma unroll
            for (int j = 0; j < 8; j++) dA8[j] = __expf(dt8[j] * Acoef);

            // phase 3: serial h chain (8 x FFMA @ 4cyc) + y
            float y8[8];
            #pragma unroll
            for (int j = 0; j < 8; j++) {
                h = dA8[j] * h + u8[j];
                y8[j] = h * ct8[j];
            }

            // phase 4: round-interleaved shfl reduction (8 independent chains)
            #pragma unroll
            for (int r = 1; r <= 8; r <<= 1) {
                #pragma unroll
                for (int j = 0; j < 8; j++)
                    y8[j] += __shfl_xor_sync(0xffffffffu, y8[j], r);
            }

            // phase 5: lead epilogue
            if (lead) {
                const __half2* pz = reinterpret_cast<const __half2*>(&c_z);
                const __half2* pxx = reinterpret_cast<const __half2*>(&c_xi);
                #pragma unroll
                for (int p = 0; p < 4; p++) {
                    float2 fz = __half22float2(pz[p]);
                    float2 fx = __half22float2(pxx[p]);
                    float s0 = fz.x / (1.f + __expf(-fz.x));
                    float s1 = fz.y / (1.f + __expf(-fz.y));
                    sout[(size_t)(tc + t0 + 2 * p) * DMODEL] =
                        __float2half_rn(y8[2 * p] * s0 + fx.x * Dd);
                    sout[(size_t)(tc + t0 + 2 * p + 1) * DMODEL] =
                        __float2half_rn(y8[2 * p + 1] * s1 + fx.y * Dd);
                }
            }

            c_dt = n_dt; c_xi = n_xi; c_z = n_z;
        }
    }
    h_out[((size_t)b * DMODEL + d) * NSTATE + n] = h;
}

// ---------------------------------------------------------------------------
// Launch
// ---------------------------------------------------------------------------
extern "C" void kernel_launch(void* const* d_in, const int* in_sizes, int n_in,
                              void* d_out, int out_size)
{
    const float* x      = (const float*)d_in[0];
    const float* h_prev = (const float*)d_in[1];
    const float* ln_g   = (const float*)d_in[2];
    const float* ln_b   = (const float*)d_in[3];
    const float* W_ig   = (const float*)d_in[4];
    const float* W_dt   = (const float*)d_in[5];
    const float* b_dt   = (const float*)d_in[6];
    const float* A_log  = (const float*)d_in[7];
    const float* W_B    = (const float*)d_in[8];
    const float* W_C    = (const float*)d_in[9];
    const float* Dv     = (const float*)d_in[10];
    const float* W_out  = (const float*)d_in[11];
    float* out = (float*)d_out;

    __half *p_xnormh, *p_xinh, *p_ssmh, *p_wigh, *p_wbch, *p_wouth;
    cudaGetSymbolAddress((void**)&p_xnormh, g_xnormh);
    cudaGetSymbolAddress((void**)&p_xinh,   g_xinh);
    cudaGetSymbolAddress((void**)&p_ssmh,   g_ssmh);
    cudaGetSymbolAddress((void**)&p_wigh,   g_wigh);
    cudaGetSymbolAddress((void**)&p_wbch,   g_wbch);
    cudaGetSymbolAddress((void**)&p_wouth,  g_wouth);

    cudaFuncSetAttribute(gemm_ma<1>, cudaFuncAttributeMaxDynamicSharedMemorySize, SMEM_DYN);
    cudaFuncSetAttribute(gemm_ma<2>, cudaFuncAttributeMaxDynamicSharedMemorySize, SMEM_DYN);
    cudaFuncSetAttribute(gemm_ma<3>, cudaFuncAttributeMaxDynamicSharedMemorySize, SMEM_DYN);

    // 0. weight prep (fp16 conversion + fused W' assembly)
    prep_kernel<<<2048, 256>>>(W_ig, W_dt, W_B, W_C, W_out);

    // 1. LayerNorm (fp16 output)
    layernorm_kernel<<<MTOT, 256>>>(x, ln_g, ln_b);

    // 2. x_proj = x_norm @ W_ig^T -> x_in (row-major fp16 + time-major fp16) | zT
    {
        dim3 grid(N1 / BN, MTOT / BM);
        gemm_ma<1><<<grid, 256, SMEM_DYN>>>(p_xnormh, p_wigh, nullptr, nullptr);
    }

    // 3. fused: dtT = softplus(x_in@W_dt^T + b_dt); btT; ctT  (all time-major)
    {
        dim3 grid(N2 / BN, MTOT / BM);
        gemm_ma<2><<<grid, 256, SMEM_DYN>>>(p_xinh, p_wbch, nullptr, b_dt);
    }

    // 4. scan -> g_ssmh (fp16), h_final -> out tail
    scan_kernel<<<BSZ * 64, 256>>>(A_log, h_prev, Dv, out + XTOT);

    // 5. out = x + ssm @ W_out^T
    {
        dim3 grid(N3 / BN, MTOT / BM);
        gemm_ma<3><<<grid, 256, SMEM_DYN>>>(p_ssmh, p_wouth, out, x);
    }
}

// round 14
// speedup vs baseline: 1.6485x; 1.0003x over previous
#include <cuda_runtime.h>
#include <cuda_fp16.h>
#include <math.h>
#include <stdint.h>

// Problem constants
#define BSZ    8
#define LSEQ   1024
#define DMODEL 1024
#define NSTATE 16
#define MTOT   (BSZ * LSEQ)        // 8192
#define XTOT   (MTOT * DMODEL)     // 8388608
#define KDIM   1024

// GEMM tiling (fp16 m16n8k16)
#define BM 128
#define BN 128
#define BK 32                       // halves per chunk (2 k16 steps)
#define NSTG 4
#define NCHUNK (KDIM / BK)          // 32
#define ROWB 80                     // 64B row + 16B pad (conflict-free, also for ldmatrix)
#define ASTAGE_B (128 * ROWB)       // 10240
#define STAGE_B  (2 * ASTAGE_B)     // 20480
#define SMEM_DYN (NSTG * STAGE_B)   // 81920

// N sizes
#define N1 2048
#define N2 1152                     // 1024 dt + 16 B + 16 C + 96 pad
#define N3 1024

// ---------------------------------------------------------------------------
// Scratch
// ---------------------------------------------------------------------------
__device__ __align__(256) __half g_xnormh[XTOT];        // fp16 (gemm1 A)
__device__ __align__(256) __half g_xinh[XTOT];          // fp16 row-major (gemm2 A)
__device__ __align__(256) __half g_xinT[XTOT];          // fp16 [b][d][t] (scan)
__device__ __align__(256) __half g_zT[XTOT];            // fp16 [b][d][t] (scan)
__device__ __align__(256) __half g_dtT[XTOT];           // fp16 [b][d][t] (scan)
__device__ __align__(256) __half g_btT[MTOT * NSTATE];  // fp16 [b][n][t]
__device__ __align__(256) __half g_ctT[MTOT * NSTATE];  // fp16 [b][n][t]
__device__ __align__(256) __half g_ssmh[XTOT];          // fp16 row-major (gemm3 A)
__device__ __align__(256) __half g_wigh[N1 * KDIM];     // fp16 W_ig
__device__ __align__(256) __half g_wbch[N2 * KDIM];     // fp16 [W_dt;W_B;W_C;0]
__device__ __align__(256) __half g_wouth[N3 * KDIM];    // fp16 W_out

// ---------------------------------------------------------------------------
// Helpers
// ---------------------------------------------------------------------------
__device__ __forceinline__ uint32_t pack_h2(float a, float b) {
    __half2 h = __floats2half2_rn(a, b);
    return *reinterpret_cast<uint32_t*>(&h);
}

__device__ __forceinline__ void mma_f16(float* c, const uint32_t* a, const uint32_t* b) {
    asm volatile(
        "mma.sync.aligned.m16n8k16.row.col.f32.f16.f16.f32 "
        "{%0,%1,%2,%3}, {%4,%5,%6,%7}, {%8,%9}, {%0,%1,%2,%3};"
        : "+f"(c[0]), "+f"(c[1]), "+f"(c[2]), "+f"(c[3])
        : "r"(a[0]), "r"(a[1]), "r"(a[2]), "r"(a[3]), "r"(b[0]), "r"(b[1]));
}

__device__ __forceinline__ void ldmx4(uint32_t& r0, uint32_t& r1, uint32_t& r2,
                                      uint32_t& r3, uint32_t addr) {
    asm volatile("ldmatrix.sync.aligned.m8n8.x4.shared.b16 {%0,%1,%2,%3}, [%4];"
                 : "=r"(r0), "=r"(r1), "=r"(r2), "=r"(r3) : "r"(addr));
}

__device__ __forceinline__ uint32_t smem_u32(const void* p) {
    uint32_t a;
    asm("{ .reg .u64 t; cvta.to.shared.u64 t, %1; cvt.u32.u64 %0, t; }" : "=r"(a) : "l"(p));
    return a;
}
__device__ __forceinline__ void cp16(uint32_t dst, const void* src) {
    asm volatile("cp.async.cg.shared.global [%0], [%1], 16;"
                 :: "r"(dst), "l"(__cvta_generic_to_global(src)));
}
#define CP_COMMIT() asm volatile("cp.async.commit_group;")
#define CP_WAIT2()  asm volatile("cp.async.wait_group 2;" ::: "memory")

__device__ __forceinline__ float softplus_f(float v) {
    return (v > 20.f) ? v : log1pf(expf(v));
}

// ---------------------------------------------------------------------------
// LayerNorm -> fp16 x_norm (only consumer is gemm1's A)
// ---------------------------------------------------------------------------
__global__ __launch_bounds__(256) void layernorm_kernel(
    const float* __restrict__ x,
    const float* __restrict__ g,
    const float* __restrict__ b)
{
    int row = blockIdx.x;
    int t = threadIdx.x;
    float4 v = reinterpret_cast<const float4*>(x + (size_t)row * DMODEL)[t];

    float s  = v.x + v.y + v.z + v.w;
    float sq = v.x * v.x + v.y * v.y + v.z * v.z + v.w * v.w;
    #pragma unroll
    for (int o = 16; o; o >>= 1) {
        s  += __shfl_xor_sync(0xffffffffu, s,  o);
        sq += __shfl_xor_sync(0xffffffffu, sq, o);
    }
    __shared__ float ssum[8], ssq[8], sh_mean, sh_rstd;
    int w = t >> 5;
    if ((t & 31) == 0) { ssum[w] = s; ssq[w] = sq; }
    __syncthreads();
    if (t == 0) {
        float S = 0.f, Q = 0.f;
        #pragma unroll
        for (int i = 0; i < 8; i++) { S += ssum[i]; Q += ssq[i]; }
        float mu  = S * (1.0f / DMODEL);
        float var = Q * (1.0f / DMODEL) - mu * mu;
        sh_mean = mu;
        sh_rstd = rsqrtf(var + 1e-5f);
    }
    __syncthreads();
    float mean = sh_mean, rstd = sh_rstd;

    float4 gg = reinterpret_cast<const float4*>(g)[t];
    float4 bb = reinterpret_cast<const float4*>(b)[t];
    uint2 o;
    o.x = pack_h2((v.x - mean) * rstd * gg.x + bb.x,
                  (v.y - mean) * rstd * gg.y + bb.y);
    o.y = pack_h2((v.z - mean) * rstd * gg.z + bb.z,
                  (v.w - mean) * rstd * gg.w + bb.w);
    reinterpret_cast<uint2*>(g_xnormh + (size_t)row * DMODEL)[t] = o;
}

// ---------------------------------------------------------------------------
// Weight prep: fp16-convert all B operands; assemble fused [W_dt; W_B; W_C; 0]
// ---------------------------------------------------------------------------
__global__ __launch_bounds__(256) void prep_kernel(
    const float* __restrict__ W_ig,
    const float* __restrict__ W_dt,
    const float* __restrict__ W_B,
    const float* __restrict__ W_C,
    const float* __restrict__ W_out)
{
    const int K4 = KDIM / 4;
    int stride = gridDim.x * blockDim.x;
    const int nig  = N1 * K4;
    const int nbc  = 1056 * K4;
    const int nout = N3 * K4;
    int total = nig + nbc + nout;
    for (int i = blockIdx.x * blockDim.x + threadIdx.x; i < total; i += stride) {
        const float4* src;
        __half* dst;
        if (i < nig) {
            src = reinterpret_cast<const float4*>(W_ig) + i;
            dst = g_wigh + (size_t)i * 4;
        } else if (i < nig + nbc) {
            int j = i - nig;
            int row = j / K4;
            int c4  = j % K4;
            const float* s;
            if (row < 1024)      s = W_dt + (size_t)row * KDIM;
            else if (row < 1040) s = W_B + (size_t)(row - 1024) * KDIM;
            else                 s = W_C + (size_t)(row - 1040) * KDIM;
            src = reinterpret_cast<const float4*>(s) + c4;
            dst = g_wbch + (size_t)j * 4;
        } else {
            int j = i - nig - nbc;
            src = reinterpret_cast<const float4*>(W_out) + j;
            dst = g_wouth + (size_t)j * 4;
        }
        float4 v = *src;
        uint2 o;
        o.x = pack_h2(v.x, v.y);
        o.y = pack_h2(v.z, v.w);
        *reinterpret_cast<uint2*>(dst) = o;
    }
}

// ---------------------------------------------------------------------------
// FP16 mma.sync m16n8k16 GEMM, cp.async 4-stage pipeline, ldmatrix fragments.
// Tile 128x128, 8 warps (2m x 4n), warp 64x32.
// EPI 1: n<1024 -> g_xinh (row-major) + g_xinT (time-major); else g_zT
// EPI 2: n<1024 -> softplus(v+aux[n]) -> g_dtT; 1024-1039 -> g_btT;
//        1040-1055 -> g_ctT; else discard
// EPI 3: O0 = v + aux[m*1024+n]  (fp32 row-major)
// ---------------------------------------------------------------------------
template<int EPI>
__global__ __launch_bounds__(256, 2) void gemm_ma(
    const __half* __restrict__ A,
    const __half* __restrict__ Bw,
    float* __restrict__ O0,
    const float* __restrict__ aux)
{
    extern __shared__ char dsm[];
    const uint32_t dsm_addr = smem_u32(dsm);

    const int tid  = threadIdx.x;
    const int wid  = tid >> 5;
    const int lane = tid & 31;
    const int bm   = blockIdx.y * BM;
    const int bn   = blockIdx.x * BN;
    const int wm   = wid >> 2;
    const int wn   = wid & 3;
    const int g    = lane >> 2;
    const int t4   = lane & 3;

    const __half* Ag = A  + (size_t)bm * KDIM;
    const __half* Bg = Bw + (size_t)bn * KDIM;

    const int lrow = tid >> 2;      // 0..63 (+it*64)
    const int lc16 = tid & 3;       // 16B column 0..3

    auto load_chunk = [&](int c, int stg) {
        uint32_t base = dsm_addr + (uint32_t)(stg * STAGE_B);
        #pragma unroll
        for (int it = 0; it < 2; it++) {
            int row = lrow + it * 64;
            cp16(base + (uint32_t)(row * ROWB + lc16 * 16),
                 Ag + (size_t)row * KDIM + c * BK + lc16 * 8);
        }
        uint32_t baseB = base + ASTAGE_B;
        #pragma unroll
        for (int it = 0; it < 2; it++) {
            int row = lrow + it * 64;
            cp16(baseB + (uint32_t)(row * ROWB + lc16 * 16),
                 Bg + (size_t)row * KDIM + c * BK + lc16 * 8);
        }
    };

    // ldmatrix per-lane row/offset patterns
    const int rowA  = (lane & 7) + ((lane >> 3) & 1) * 8;  // A: m within 16
    const int koffA = (lane >> 4) * 16;                    // A: k-half select
    const int rowB  = (lane & 7) + (lane >> 4) * 8;        // B: n within 16
    const int koffB = ((lane >> 3) & 1) * 16;              // B: k-half select

    float acc[4][4][4];
    #pragma unroll
    for (int i = 0; i < 4; i++)
        #pragma unroll
        for (int j = 0; j < 4; j++)
            #pragma unroll
            for (int r = 0; r < 4; r++) acc[i][j][r] = 0.f;

    // prologue: chunks 0,1,2
    load_chunk(0, 0); CP_COMMIT();
    load_chunk(1, 1); CP_COMMIT();
    load_chunk(2, 2); CP_COMMIT();

    for (int c = 0; c < NCHUNK; c++) {
        CP_WAIT2();
        __syncthreads();

        if (c + 3 < NCHUNK) { load_chunk(c + 3, (c + 3) & (NSTG - 1)); CP_COMMIT(); }

        uint32_t sbase = dsm_addr + (uint32_t)((c & (NSTG - 1)) * STAGE_B);
        uint32_t aAddr = sbase + (uint32_t)((wm * 64 + rowA) * ROWB + koffA);
        uint32_t bAddr = sbase + ASTAGE_B + (uint32_t)((wn * 32 + rowB) * ROWB + koffB);

        #pragma unroll
        for (int s = 0; s < 2; s++) {
            const int ko = s * 32;   // byte offset of this k16 step
            uint32_t bf[4][2];
            #pragma unroll
            for (int np = 0; np < 2; np++)
                ldmx4(bf[2 * np][0], bf[2 * np][1], bf[2 * np + 1][0], bf[2 * np + 1][1],
                      bAddr + (uint32_t)(np * 16 * ROWB + ko));
            #pragma unroll
            for (int mt = 0; mt < 4; mt++) {
                uint32_t af[4];
                ldmx4(af[0], af[1], af[2], af[3],
                      aAddr + (uint32_t)(mt * 16 * ROWB + ko));
                #pragma unroll
                for (int nt = 0; nt < 4; nt++)
                    mma_f16(acc[mt][nt], af, bf[nt]);
            }
        }
    }

    // Epilogue
    #pragma unroll
    for (int mt = 0; mt < 4; mt++) {
        #pragma unroll
        for (int nt = 0; nt < 4; nt++) {
            int m0 = bm + wm * 64 + mt * 16 + g;
            int n0 = bn + wn * 32 + nt * 8 + 2 * t4;
            float* cc = acc[mt][nt];
            #pragma unroll
            for (int half_i = 0; half_i < 2; half_i++) {
                int m = m0 + half_i * 8;
                int bb = m >> 10;
                int tt = m & 1023;
                float v0 = cc[half_i * 2 + 0];
                float v1 = cc[half_i * 2 + 1];
                if constexpr (EPI == 1) {
                    if (n0 < DMODEL) {
                        *reinterpret_cast<uint32_t*>(&g_xinh[(size_t)m * DMODEL + n0]) = pack_h2(v0, v1);
                        g_xinT[((size_t)bb * DMODEL + n0) * LSEQ + tt]     = __float2half_rn(v0);
                        g_xinT[((size_t)bb * DMODEL + n0 + 1) * LSEQ + tt] = __float2half_rn(v1);
                    } else {
                        int dd = n0 - DMODEL;
                        g_zT[((size_t)bb * DMODEL + dd) * LSEQ + tt]     = __float2half_rn(v0);
                        g_zT[((size_t)bb * DMODEL + dd + 1) * LSEQ + tt] = __float2half_rn(v1);
                    }
                } else if constexpr (EPI == 2) {
                    if (n0 < DMODEL) {
                        v0 = softplus_f(v0 + aux[n0]);
                        v1 = softplus_f(v1 + aux[n0 + 1]);
                        g_dtT[((size_t)bb * DMODEL + n0) * LSEQ + tt]     = __float2half_rn(v0);
                        g_dtT[((size_t)bb * DMODEL + n0 + 1) * LSEQ + tt] = __float2half_rn(v1);
                    } else if (n0 < 1040) {
                        int j = n0 - 1024;
                        g_btT[((size_t)bb * NSTATE + j) * LSEQ + tt]     = __float2half_rn(v0);
                        g_btT[((size_t)bb * NSTATE + j + 1) * LSEQ + tt] = __float2half_rn(v1);
                    } else if (n0 < 1056) {
                        int j = n0 - 1040;
                        g_ctT[((size_t)bb * NSTATE + j) * LSEQ + tt]     = __float2half_rn(v0);
                        g_ctT[((size_t)bb * NSTATE + j + 1) * LSEQ + tt] = __float2half_rn(v1);
                    }
                } else { // EPI == 3
                    float2 r = *reinterpret_cast<const float2*>(&aux[(size_t)m * DMODEL + n0]);
                    *reinterpret_cast<float2*>(&O0[(size_t)m * DMODEL + n0]) = make_float2(v0 + r.x, v1 + r.y);
                }
            }
        }
    }
}

// ---------------------------------------------------------------------------
// Sequential SSM scan, time-major fp16 inputs, bt/ct staged through SMEM.
// R13: phase-restructured 8-step block for explicit cross-step ILP:
//   batch cvt -> batch exp -> 8-FMA h chain -> round-interleaved shfls ->
//   lead epilogue. Arithmetic order on h identical to R12 (bitwise same).
// ---------------------------------------------------------------------------
#define TCH 256
__global__ __launch_bounds__(256, 3) void scan_kernel(
    const float* __restrict__ A_log,
    const float* __restrict__ h_prev,
    const float* __restrict__ Dvec,
    float* __restrict__ h_out)
{
    __shared__ __half sbt[16][TCH + 8];
    __shared__ __half sct[16][TCH + 8];

    int tid = threadIdx.x;
    int b  = blockIdx.x >> 6;
    int dg = blockIdx.x & 63;
    int n  = tid & 15;
    int dl = tid >> 4;
    int d  = dg * 16 + dl;

    float Acoef = -__expf(A_log[d * NSTATE + n]);
    float h  = h_prev[((size_t)b * DMODEL + d) * NSTATE + n];
    float Dd = Dvec[d];
    const bool lead = (n == 0);

    const uint4* dtp = reinterpret_cast<const uint4*>(g_dtT  + ((size_t)b * DMODEL + d) * LSEQ);
    const uint4* xip = reinterpret_cast<const uint4*>(g_xinT + ((size_t)b * DMODEL + d) * LSEQ);
    const uint4* ztp = reinterpret_cast<const uint4*>(g_zT   + ((size_t)b * DMODEL + d) * LSEQ);
    const __half* btg = g_btT + (size_t)b * NSTATE * LSEQ;
    const __half* ctg = g_ctT + (size_t)b * NSTATE * LSEQ;
    __half* sout = g_ssmh + (size_t)b * LSEQ * DMODEL + d;

    uint4 c_dt = dtp[0];
    uint4 c_xi = xip[0];
    uint4 c_z  = lead ? ztp[0] : make_uint4(0, 0, 0, 0);

    for (int tc = 0; tc < LSEQ; tc += TCH) {
        __syncthreads();   // all reads of previous chunk's tiles done
        #pragma unroll
        for (int it = 0; it < 2; it++) {
            int i = tid + it * 256;
            int row = i >> 5;          // 0..15
            int col = i & 31;          // uint4 column
            *reinterpret_cast<uint4*>(&sbt[row][col * 8]) =
                *reinterpret_cast<const uint4*>(btg + (size_t)row * LSEQ + tc + col * 8);
            *reinterpret_cast<uint4*>(&sct[row][col * 8]) =
                *reinterpret_cast<const uint4*>(ctg + (size_t)row * LSEQ + tc + col * 8);
        }
        __syncthreads();

        for (int t0 = 0; t0 < TCH; t0 += 8) {
            int gblk = (tc + t0) >> 3;
            uint4 n_dt, n_xi, n_z;
            if (gblk + 1 < LSEQ / 8) {
                n_dt = dtp[gblk + 1];
                n_xi = xip[gblk + 1];
                n_z  = lead ? ztp[gblk + 1] : make_uint4(0, 0, 0, 0);
            } else {
                n_dt = n_xi = n_z = make_uint4(0, 0, 0, 0);
            }

            uint4 c_bt = *reinterpret_cast<const uint4*>(&sbt[n][t0]);
            uint4 c_ct = *reinterpret_cast<const uint4*>(&sct[n][t0]);

            const __half2* pd = reinterpret_cast<const __half2*>(&c_dt);
            const __half2* px = reinterpret_cast<const __half2*>(&c_xi);
            const __half2* pb = reinterpret_cast<const __half2*>(&c_bt);
            const __half2* pc = reinterpret_cast<const __half2*>(&c_ct);

            // phase 1: batch convert + u = (dt*xi)*bt, ct stash
            float dt8[8], u8[8], ct8[8];
            #pragma unroll
            for (int p = 0; p < 4; p++) {
                float2 fd = __half22float2(pd[p]);
                float2 fx = __half22float2(px[p]);
                float2 fb = __half22float2(pb[p]);
                float2 fc = __half22float2(pc[p]);
                dt8[2 * p]     = fd.x;  dt8[2 * p + 1] = fd.y;
                u8[2 * p]      = (fd.x * fx.x) * fb.x;
                u8[2 * p + 1]  = (fd.y * fx.y) * fb.y;
                ct8[2 * p]     = fc.x;  ct8[2 * p + 1] = fc.y;
            }

            // phase 2: batch exp (MUFU pipelined, independent of h)
            float dA8[8];
            #pragma unroll
            for (int j = 0; j < 8; j++) dA8[j] = __expf(dt8[j] * Acoef);

            // phase 3: serial h chain (8 x FFMA @ 4cyc) + y
            float y8[8];
            #pragma unroll
            for (int j = 0; j < 8; j++) {
                h = dA8[j] * h + u8[j];
                y8[j] = h * ct8[j];
            }

            // phase 4: round-interleaved shfl reduction (8 independent chains)
            #pragma unroll
            for (int r = 1; r <= 8; r <<= 1) {
                #pragma unroll
                for (int j = 0; j < 8; j++)
                    y8[j] += __shfl_xor_sync(0xffffffffu, y8[j], r);
            }

            // phase 5: lead epilogue
            if (lead) {
                const __half2* pz = reinterpret_cast<const __half2*>(&c_z);
                const __half2* pxx = reinterpret_cast<const __half2*>(&c_xi);
                #pragma unroll
                for (int p = 0; p < 4; p++) {
                    float2 fz = __half22float2(pz[p]);
                    float2 fx = __half22float2(pxx[p]);
                    float s0 = fz.x / (1.f + __expf(-fz.x));
                    float s1 = fz.y / (1.f + __expf(-fz.y));
                    sout[(size_t)(tc + t0 + 2 * p) * DMODEL] =
                        __float2half_rn(y8[2 * p] * s0 + fx.x * Dd);
                    sout[(size_t)(tc + t0 + 2 * p + 1) * DMODEL] =
                        __float2half_rn(y8[2 * p + 1] * s1 + fx.y * Dd);
                }
            }

            c_dt = n_dt; c_xi = n_xi; c_z = n_z;
        }
    }
    h_out[((size_t)b * DMODEL + d) * NSTATE + n] = h;
}

// ---------------------------------------------------------------------------
// Launch
// ---------------------------------------------------------------------------
extern "C" void kernel_launch(void* const* d_in, const int* in_sizes, int n_in,
                              void* d_out, int out_size)
{
    const float* x      = (const float*)d_in[0];
    const float* h_prev = (const float*)d_in[1];
    const float* ln_g   = (const float*)d_in[2];
    const float* ln_b   = (const float*)d_in[3];
    const float* W_ig   = (const float*)d_in[4];
    const float* W_dt   = (const float*)d_in[5];
    const float* b_dt   = (const float*)d_in[6];
    const float* A_log  = (const float*)d_in[7];
    const float* W_B    = (const float*)d_in[8];
    const float* W_C    = (const float*)d_in[9];
    const float* Dv     = (const float*)d_in[10];
    const float* W_out  = (const float*)d_in[11];
    float* out = (float*)d_out;

    __half *p_xnormh, *p_xinh, *p_ssmh, *p_wigh, *p_wbch, *p_wouth;
    cudaGetSymbolAddress((void**)&p_xnormh, g_xnormh);
    cudaGetSymbolAddress((void**)&p_xinh,   g_xinh);
    cudaGetSymbolAddress((void**)&p_ssmh,   g_ssmh);
    cudaGetSymbolAddress((void**)&p_wigh,   g_wigh);
    cudaGetSymbolAddress((void**)&p_wbch,   g_wbch);
    cudaGetSymbolAddress((void**)&p_wouth,  g_wouth);

    cudaFuncSetAttribute(gemm_ma<1>, cudaFuncAttributeMaxDynamicSharedMemorySize, SMEM_DYN);
    cudaFuncSetAttribute(gemm_ma<2>, cudaFuncAttributeMaxDynamicSharedMemorySize, SMEM_DYN);
    cudaFuncSetAttribute(gemm_ma<3>, cudaFuncAttributeMaxDynamicSharedMemorySize, SMEM_DYN);

    // 0. weight prep (fp16 conversion + fused W' assembly)
    prep_kernel<<<2048, 256>>>(W_ig, W_dt, W_B, W_C, W_out);

    // 1. LayerNorm (fp16 output)
    layernorm_kernel<<<MTOT, 256>>>(x, ln_g, ln_b);

    // 2. x_proj = x_norm @ W_ig^T -> x_in (row-major fp16 + time-major fp16) | zT
    {
        dim3 grid(N1 / BN, MTOT / BM);
        gemm_ma<1><<<grid, 256, SMEM_DYN>>>(p_xnormh, p_wigh, nullptr, nullptr);
    }

    // 3. fused: dtT = softplus(x_in@W_dt^T + b_dt); btT; ctT  (all time-major)
    {
        dim3 grid(N2 / BN, MTOT / BM);
        gemm_ma<2><<<grid, 256, SMEM_DYN>>>(p_xinh, p_wbch, nullptr, b_dt);
    }

    // 4. scan -> g_ssmh (fp16), h_final -> out tail
    scan_kernel<<<BSZ * 64, 256>>>(A_log, h_prev, Dv, out + XTOT);

    // 5. out = x + ssm @ W_out^T
    {
        dim3 grid(N3 / BN, MTOT / BM);
        gemm_ma<3><<<grid, 256, SMEM_DYN>>>(p_ssmh, p_wouth, out, x);
    }
}